// round 3
// baseline (speedup 1.0000x reference)
#include <cuda_runtime.h>

#define B_   4
#define N_   40
#define NC   64000      // 40^3
#define RT   256000     // B * N^3
#define F_   128
#define H_   128
#define SAS  66         // transposed-tile smem stride (even -> 8B-aligned pairs)

typedef unsigned long long u64;

// scratch (device globals per allocation rules)
__device__ float g_xembed[(size_t)RT * H_];
__device__ float g_sumexp[B_ * H_];
__device__ int   g_len[B_];
// duplicated weights: wd[k*C + c] = (W[k][c], W[k][c]) packed in u64
__device__ u64 g_wd_i1[128 * 128];
__device__ u64 g_wd_i2[128 * 128];
__device__ u64 g_wd_e [128 * 128];
__device__ u64 g_wd_o1[256 * 256];

// ---- packed f32x2 helpers ----
static __device__ __forceinline__ u64 pack2(float a, float b) {
    u64 r;
    asm("mov.b64 %0, {%1, %2};" : "=l"(r) : "f"(a), "f"(b));
    return r;
}
static __device__ __forceinline__ void ffma2(u64& d, u64 a, u64 b) {
    asm("fma.rn.f32x2 %0, %1, %2, %0;" : "+l"(d) : "l"(a), "l"(b));
}
static __device__ __forceinline__ float2 unpack2(u64 v) {
    float2 f;
    asm("mov.b64 {%0, %1}, %2;" : "=f"(f.x), "=f"(f.y) : "l"(v));
    return f;
}

// one k-step: acc[pair][c] += (A[2p][k],A[2p+1][k]) * Wdup[k][c0+c]
// A pairs come straight from transposed smem (LDS.64), W pairs from dup'd
// global (LDG.128 x2). Zero packing instructions in the loop.
#define GEMM_K_STEP(ACC, SAT_ROW, WD_ROW)                                   \
    do {                                                                     \
        ulonglong2 _wA = *(const ulonglong2*)((WD_ROW));                     \
        ulonglong2 _wB = *(const ulonglong2*)((WD_ROW) + 2);                 \
        u64 _a0 = *(const u64*)((SAT_ROW) + 0);                              \
        u64 _a1 = *(const u64*)((SAT_ROW) + 2);                              \
        u64 _a2 = *(const u64*)((SAT_ROW) + 4);                              \
        u64 _a3 = *(const u64*)((SAT_ROW) + 6);                              \
        ffma2((ACC)[0][0], _a0, _wA.x); ffma2((ACC)[0][1], _a0, _wA.y);      \
        ffma2((ACC)[0][2], _a0, _wB.x); ffma2((ACC)[0][3], _a0, _wB.y);      \
        ffma2((ACC)[1][0], _a1, _wA.x); ffma2((ACC)[1][1], _a1, _wA.y);      \
        ffma2((ACC)[1][2], _a1, _wB.x); ffma2((ACC)[1][3], _a1, _wB.y);      \
        ffma2((ACC)[2][0], _a2, _wA.x); ffma2((ACC)[2][1], _a2, _wA.y);      \
        ffma2((ACC)[2][2], _a2, _wB.x); ffma2((ACC)[2][3], _a2, _wB.y);      \
        ffma2((ACC)[3][0], _a3, _wA.x); ffma2((ACC)[3][1], _a3, _wA.y);      \
        ffma2((ACC)[3][2], _a3, _wB.x); ffma2((ACC)[3][3], _a3, _wB.y);      \
    } while (0)

// ---------------------------------------------------------------------------
// Kernel 0a: mask -> lengths, zero softmax denominators.
// ---------------------------------------------------------------------------
__global__ void k_setup(const unsigned char* __restrict__ mraw) {
    int t = threadIdx.x;
    if (t < B_ * H_) g_sumexp[t] = 0.f;
    if (t < B_) {
        int cnt = 0;
        if (mraw[1] != 0) {
            for (int j = 0; j < N_; j++) cnt += (mraw[t * N_ + j] != 0) ? 1 : 0;
        } else {
            const unsigned int* mi = (const unsigned int*)mraw;
            for (int j = 0; j < N_; j++) cnt += (mi[t * N_ + j] != 0u) ? 1 : 0;
        }
        g_len[t] = cnt;
    }
}

// ---------------------------------------------------------------------------
// Kernel 0b: duplicate weights into u64 (w,w) pairs.
// ---------------------------------------------------------------------------
__global__ void k_dup(const float* __restrict__ Wi1, const float* __restrict__ Wi2,
                      const float* __restrict__ We,  const float* __restrict__ Wo1) {
    int i = blockIdx.x * 256 + threadIdx.x;
    if (i < 16384)      { float v = Wi1[i];          g_wd_i1[i]          = pack2(v, v); }
    else if (i < 32768) { float v = Wi2[i - 16384];  g_wd_i2[i - 16384]  = pack2(v, v); }
    else if (i < 49152) { float v = We [i - 32768];  g_wd_e [i - 32768]  = pack2(v, v); }
    else if (i < 114688){ float v = Wo1[i - 49152];  g_wd_o1[i - 49152]  = pack2(v, v); }
}

// ---------------------------------------------------------------------------
// Kernel 1: x_embed = relu(x @ Wi1 + bi1) @ Wi2 + bi2, + sumexp accumulation.
// Activation tile kept TRANSPOSED in smem; FFMA2 row-pair accumulators.
// ---------------------------------------------------------------------------
__global__ __launch_bounds__(256) void k_embed(
    const float* __restrict__ x,
    const float* __restrict__ bi1, const float* __restrict__ bi2)
{
    __shared__ float sAT[128 * SAS];   // [k][m] transposed tile
    __shared__ float sSum[128];

    const int row0 = blockIdx.x * 64;
    const int b    = row0 / NC;
    const int t    = threadIdx.x;
    const int cg   = t & 31;
    const int wg   = t >> 5;
    const int c0   = cg * 4;
    const int m0   = wg * 8;

    // load x tile transposed
    {
        const float4* xg = (const float4*)(x + (size_t)row0 * F_);
        #pragma unroll
        for (int i = 0; i < 8; i++) {
            float4 v = xg[t + i * 256];
            int e   = 4 * (t + i * 256);
            int row = e >> 7;
            int k   = e & 127;
            sAT[(k + 0) * SAS + row] = v.x;
            sAT[(k + 1) * SAS + row] = v.y;
            sAT[(k + 2) * SAS + row] = v.z;
            sAT[(k + 3) * SAS + row] = v.w;
        }
    }
    if (t < 128) sSum[t] = 0.f;
    __syncthreads();

    u64 acc[4][4];

    // ---- GEMM1: y1 = relu(x @ Wi1 + bi1) ----
    {
        #pragma unroll
        for (int c = 0; c < 4; c++) {
            u64 bv = pack2(bi1[c0 + c], bi1[c0 + c]);
            #pragma unroll
            for (int p = 0; p < 4; p++) acc[p][c] = bv;
        }
    }
    #pragma unroll 4
    for (int k = 0; k < 128; k++) {
        GEMM_K_STEP(acc, &sAT[k * SAS + m0], g_wd_i1 + k * 128 + c0);
    }
    __syncthreads();   // all warps done reading x tile
    #pragma unroll
    for (int p = 0; p < 4; p++) {
        #pragma unroll
        for (int c = 0; c < 4; c++) {
            float2 v = unpack2(acc[p][c]);
            u64 r = pack2(fmaxf(v.x, 0.f), fmaxf(v.y, 0.f));
            *(u64*)(&sAT[(c0 + c) * SAS + m0 + 2 * p]) = r;  // transposed y1
        }
    }
    __syncthreads();

    // ---- GEMM2: y2 = y1 @ Wi2 + bi2 ----
    {
        #pragma unroll
        for (int c = 0; c < 4; c++) {
            u64 bv = pack2(bi2[c0 + c], bi2[c0 + c]);
            #pragma unroll
            for (int p = 0; p < 4; p++) acc[p][c] = bv;
        }
    }
    #pragma unroll 4
    for (int k = 0; k < 128; k++) {
        GEMM_K_STEP(acc, &sAT[k * SAS + m0], g_wd_i2 + k * 128 + c0);
    }

    // ---- store x_embed + accumulate sumexp over valid hyperedges ----
    const int lenb = g_len[b];
    float4 es = make_float4(0.f, 0.f, 0.f, 0.f);
    bool any = false;
    #pragma unroll
    for (int p = 0; p < 4; p++) {
        const int r0g = row0 + m0 + 2 * p;
        float2 v0 = unpack2(acc[p][0]);
        float2 v1 = unpack2(acc[p][1]);
        float2 v2 = unpack2(acc[p][2]);
        float2 v3 = unpack2(acc[p][3]);
        float4 lo = make_float4(v0.x, v1.x, v2.x, v3.x);   // row r0g
        float4 hi = make_float4(v0.y, v1.y, v2.y, v3.y);   // row r0g+1
        *(float4*)(g_xembed + (size_t)r0g * 128 + c0)       = lo;
        *(float4*)(g_xembed + (size_t)(r0g + 1) * 128 + c0) = hi;
        #pragma unroll
        for (int h = 0; h < 2; h++) {
            const int rem = r0g + h - b * NC;
            const int i  = rem / 1600;
            const int j  = (rem / 40) % 40;
            const int kk = rem % 40;
            if (i < j && j < kk && kk < lenb) {
                float4 v = h ? hi : lo;
                es.x += __expf(v.x);
                es.y += __expf(v.y);
                es.z += __expf(v.z);
                es.w += __expf(v.w);
                any = true;
            }
        }
    }
    if (any) {
        atomicAdd(&sSum[c0 + 0], es.x);
        atomicAdd(&sSum[c0 + 1], es.y);
        atomicAdd(&sSum[c0 + 2], es.z);
        atomicAdd(&sSum[c0 + 3], es.w);
    }
    __syncthreads();
    if (t < 128) {
        float v = sSum[t];
        if (v != 0.f) atomicAdd(&g_sumexp[b * 128 + t], v);
    }
}

// ---------------------------------------------------------------------------
// Kernel 2: out = relu([a * relu(xf@We), xf] @ Wo1 + bo1) @ Wo2 + bo2
// ---------------------------------------------------------------------------
extern __shared__ float smem2[];
__global__ __launch_bounds__(256) void k_out(
    const float* __restrict__ bo1,
    const float* __restrict__ Wo2, const float* __restrict__ bo2,
    float* __restrict__ out)
{
    float* sXFT  = smem2;                  // 128*SAS (transposed xf tile)
    float* sAXIT = smem2 + 128 * SAS;      // 128*SAS (transposed a*x_inner)
    float* sInv  = smem2 + 2 * 128 * SAS;  // 128

    const int row0 = blockIdx.x * 64;
    const int b    = row0 / NC;
    const int t    = threadIdx.x;
    const int cg   = t & 31;
    const int wg   = t >> 5;
    const int c0   = cg * 4;
    const int m0   = wg * 8;

    {
        const float4* xg = (const float4*)(g_xembed + (size_t)row0 * 128);
        #pragma unroll
        for (int i = 0; i < 8; i++) {
            float4 v = xg[t + i * 256];
            int e   = 4 * (t + i * 256);
            int row = e >> 7;
            int k   = e & 127;
            sXFT[(k + 0) * SAS + row] = v.x;
            sXFT[(k + 1) * SAS + row] = v.y;
            sXFT[(k + 2) * SAS + row] = v.z;
            sXFT[(k + 3) * SAS + row] = v.w;
        }
    }
    if (t < 128) sInv[t] = 1.0f / g_sumexp[b * 128 + t];
    __syncthreads();

    const int lenb = g_len[b];
    bool valid[8];
    bool any = false;
    #pragma unroll
    for (int m = 0; m < 8; m++) {
        const int rem = row0 + m0 + m - b * NC;
        const int i  = rem / 1600;
        const int j  = (rem / 40) % 40;
        const int kk = rem % 40;
        valid[m] = (i < j) && (j < kk) && (kk < lenb);
        any |= valid[m];
    }

    // ---- stage A (valid warps only): axi = a .* relu(xf @ We), stored transposed ----
    if (any) {
        u64 acc[4][4];
        #pragma unroll
        for (int p = 0; p < 4; p++)
            #pragma unroll
            for (int c = 0; c < 4; c++) acc[p][c] = 0ull;
        #pragma unroll 4
        for (int k = 0; k < 128; k++) {
            GEMM_K_STEP(acc, &sXFT[k * SAS + m0], g_wd_e + k * 128 + c0);
        }
        float4 inv4 = *(const float4*)(&sInv[c0]);
        const float invc[4] = {inv4.x, inv4.y, inv4.z, inv4.w};
        #pragma unroll
        for (int p = 0; p < 4; p++) {
            const int r0 = m0 + 2 * p;
            const bool v0 = valid[2 * p], v1 = valid[2 * p + 1];
            #pragma unroll
            for (int c = 0; c < 4; c++) {
                float2 a2 = unpack2(acc[p][c]);
                float xf0 = sXFT[(c0 + c) * SAS + r0];
                float xf1 = sXFT[(c0 + c) * SAS + r0 + 1];
                float o0 = v0 ? __expf(xf0) * invc[c] * fmaxf(a2.x, 0.f) : 0.f;
                float o1 = v1 ? __expf(xf1) * invc[c] * fmaxf(a2.y, 0.f) : 0.f;
                *(u64*)(&sAXIT[(c0 + c) * SAS + r0]) = pack2(o0, o1);
            }
        }
        __syncwarp();
    }

    // ---- stage B: g = relu(h @ Wo1 + bo1); out = g @ Wo2 + bo2 ----
    float rsum[8];
    #pragma unroll
    for (int m = 0; m < 8; m++) rsum[m] = 0.f;

    #pragma unroll
    for (int half = 0; half < 2; half++) {
        const int n0 = half * 128 + c0;
        u64 g[4][4];
        #pragma unroll
        for (int c = 0; c < 4; c++) {
            u64 bv = pack2(bo1[n0 + c], bo1[n0 + c]);
            #pragma unroll
            for (int p = 0; p < 4; p++) g[p][c] = bv;
        }
        // xf part: Wo1 rows 128..255
        #pragma unroll 4
        for (int k = 0; k < 128; k++) {
            GEMM_K_STEP(g, &sXFT[k * SAS + m0], g_wd_o1 + (128 + k) * 256 + n0);
        }
        // a*x_inner part: Wo1 rows 0..127 (skipped when no valid row in warp)
        if (any) {
            #pragma unroll 4
            for (int k = 0; k < 128; k++) {
                GEMM_K_STEP(g, &sAXIT[k * SAS + m0], g_wd_o1 + k * 256 + n0);
            }
        }
        float4 w2v = *(const float4*)(Wo2 + n0);
        #pragma unroll
        for (int p = 0; p < 4; p++) {
            float2 v0 = unpack2(g[p][0]);
            float2 v1 = unpack2(g[p][1]);
            float2 v2 = unpack2(g[p][2]);
            float2 v3 = unpack2(g[p][3]);
            rsum[2 * p]     += fmaxf(v0.x, 0.f) * w2v.x + fmaxf(v1.x, 0.f) * w2v.y
                             + fmaxf(v2.x, 0.f) * w2v.z + fmaxf(v3.x, 0.f) * w2v.w;
            rsum[2 * p + 1] += fmaxf(v0.y, 0.f) * w2v.x + fmaxf(v1.y, 0.f) * w2v.y
                             + fmaxf(v2.y, 0.f) * w2v.z + fmaxf(v3.y, 0.f) * w2v.w;
        }
    }

    #pragma unroll
    for (int off = 16; off; off >>= 1) {
        #pragma unroll
        for (int m = 0; m < 8; m++)
            rsum[m] += __shfl_xor_sync(0xffffffffu, rsum[m], off);
    }
    if (cg == 0) {
        const float b2 = bo2[0];
        #pragma unroll
        for (int m = 0; m < 8; m++)
            out[row0 + m0 + m] = rsum[m] + b2;
    }
}

// ---------------------------------------------------------------------------
extern "C" void kernel_launch(void* const* d_in, const int* in_sizes, int n_in,
                              void* d_out, int out_size) {
    const float* x          = (const float*)d_in[0];
    const unsigned char* mk = (const unsigned char*)d_in[1];
    const float* Wi1        = (const float*)d_in[2];
    const float* bi1        = (const float*)d_in[3];
    const float* Wi2        = (const float*)d_in[4];
    const float* bi2        = (const float*)d_in[5];
    const float* We         = (const float*)d_in[6];
    const float* Wo1        = (const float*)d_in[7];
    const float* bo1        = (const float*)d_in[8];
    const float* Wo2        = (const float*)d_in[9];
    const float* bo2        = (const float*)d_in[10];
    float* out              = (float*)d_out;

    const int smem_k_out = (2 * 128 * SAS + 128) * (int)sizeof(float);  // ~68 KB
    cudaFuncSetAttribute(k_out, cudaFuncAttributeMaxDynamicSharedMemorySize, smem_k_out);

    k_setup<<<1, 512>>>(mk);
    k_dup<<<448, 256>>>(Wi1, Wi2, We, Wo1);
    k_embed<<<RT / 64, 256>>>(x, bi1, bi2);
    k_out<<<RT / 64, 256, smem_k_out>>>(bo1, Wo2, bo2, out);
}

// round 4
// speedup vs baseline: 1.4990x; 1.4990x over previous
#include <cuda_runtime.h>

#define B_   4
#define N_   40
#define NC   64000      // 40^3
#define RT   256000     // B * N^3
#define F_   128
#define H_   128
#define SAS  68         // transposed-tile stride: (k*68+m0)*4 is 16B-aligned

typedef unsigned long long u64;

// scratch (device globals per allocation rules)
__device__ float g_xembed[(size_t)RT * H_];
__device__ float g_sumexp[B_ * H_];
__device__ int   g_len[B_];

// ---- packed f32x2 helpers ----
static __device__ __forceinline__ u64 pack2(float a, float b) {
    u64 r;
    asm("mov.b64 %0, {%1, %2};" : "=l"(r) : "f"(a), "f"(b));
    return r;
}
static __device__ __forceinline__ void ffma2(u64& d, u64 a, u64 b) {
    asm("fma.rn.f32x2 %0, %1, %2, %0;" : "+l"(d) : "l"(a), "l"(b));
}
static __device__ __forceinline__ float2 unpack2(u64 v) {
    float2 f;
    asm("mov.b64 {%0, %1}, %2;" : "=f"(f.x), "=f"(f.y) : "l"(v));
    return f;
}

// one k-step: acc[pair][c] += (A[2p][k],A[2p+1][k]) * W[k][c0+c]
// A: 2x LDS.128 broadcast from transposed smem; W: 1x LDG.128 (original
// weights) duplicated into both f32x2 lanes via 4 register packs.
#define GEMM_K_STEP(ACC, SAT_ROW, W_ROW)                                     \
    do {                                                                     \
        float4 _w = *(const float4*)(W_ROW);                                 \
        u64 _w0 = pack2(_w.x, _w.x);                                         \
        u64 _w1 = pack2(_w.y, _w.y);                                         \
        u64 _w2 = pack2(_w.z, _w.z);                                         \
        u64 _w3 = pack2(_w.w, _w.w);                                         \
        ulonglong2 _aA = *(const ulonglong2*)((SAT_ROW));                    \
        ulonglong2 _aB = *(const ulonglong2*)((SAT_ROW) + 4);                \
        ffma2((ACC)[0][0], _aA.x, _w0); ffma2((ACC)[0][1], _aA.x, _w1);      \
        ffma2((ACC)[0][2], _aA.x, _w2); ffma2((ACC)[0][3], _aA.x, _w3);      \
        ffma2((ACC)[1][0], _aA.y, _w0); ffma2((ACC)[1][1], _aA.y, _w1);      \
        ffma2((ACC)[1][2], _aA.y, _w2); ffma2((ACC)[1][3], _aA.y, _w3);      \
        ffma2((ACC)[2][0], _aB.x, _w0); ffma2((ACC)[2][1], _aB.x, _w1);      \
        ffma2((ACC)[2][2], _aB.x, _w2); ffma2((ACC)[2][3], _aB.x, _w3);      \
        ffma2((ACC)[3][0], _aB.y, _w0); ffma2((ACC)[3][1], _aB.y, _w1);      \
        ffma2((ACC)[3][2], _aB.y, _w2); ffma2((ACC)[3][3], _aB.y, _w3);      \
    } while (0)

// ---------------------------------------------------------------------------
// Kernel 0: mask -> lengths, zero softmax denominators.
// ---------------------------------------------------------------------------
__global__ void k_setup(const unsigned char* __restrict__ mraw) {
    int t = threadIdx.x;
    if (t < B_ * H_) g_sumexp[t] = 0.f;
    if (t < B_) {
        int cnt = 0;
        if (mraw[1] != 0) {
            for (int j = 0; j < N_; j++) cnt += (mraw[t * N_ + j] != 0) ? 1 : 0;
        } else {
            const unsigned int* mi = (const unsigned int*)mraw;
            for (int j = 0; j < N_; j++) cnt += (mi[t * N_ + j] != 0u) ? 1 : 0;
        }
        g_len[t] = cnt;
    }
}

// transposed tile loader: gmem row-major float4 -> smem [k][row], with a
// lane-rotated component order so STS.32 bank conflicts drop to ~4-way.
static __device__ __forceinline__ void load_tile_T(
    const float* __restrict__ src, float* __restrict__ sT, int t)
{
    const float4* xg = (const float4*)src;
    #pragma unroll
    for (int i = 0; i < 8; i++) {
        float4 v = xg[t + i * 256];
        float vv[4] = {v.x, v.y, v.z, v.w};
        int e   = 4 * (t + i * 256);
        int row = e >> 7;
        int k   = e & 127;
        #pragma unroll
        for (int jj = 0; jj < 4; jj++) {
            int j = (jj + t) & 3;
            sT[(k + j) * SAS + row] = vv[j];
        }
    }
}

// ---------------------------------------------------------------------------
// Kernel 1: x_embed = relu(x @ Wi1 + bi1) @ Wi2 + bi2, + sumexp accumulation.
// ---------------------------------------------------------------------------
__global__ __launch_bounds__(256) void k_embed(
    const float* __restrict__ x,
    const float* __restrict__ Wi1, const float* __restrict__ bi1,
    const float* __restrict__ Wi2, const float* __restrict__ bi2)
{
    __shared__ __align__(16) float sAT[128 * SAS];   // [k][m] transposed tile
    __shared__ float sSum[128];

    const int row0 = blockIdx.x * 64;
    const int b    = row0 / NC;
    const int t    = threadIdx.x;
    const int cg   = t & 31;
    const int wg   = t >> 5;
    const int c0   = cg * 4;
    const int m0   = wg * 8;

    load_tile_T(x + (size_t)row0 * F_, sAT, t);
    if (t < 128) sSum[t] = 0.f;
    __syncthreads();

    u64 acc[4][4];

    // ---- GEMM1: y1 = relu(x @ Wi1 + bi1) ----
    #pragma unroll
    for (int c = 0; c < 4; c++) {
        u64 bv = pack2(bi1[c0 + c], bi1[c0 + c]);
        #pragma unroll
        for (int p = 0; p < 4; p++) acc[p][c] = bv;
    }
    #pragma unroll 4
    for (int k = 0; k < 128; k++) {
        GEMM_K_STEP(acc, &sAT[k * SAS + m0], Wi1 + k * 128 + c0);
    }
    __syncthreads();   // all warps done reading x tile
    #pragma unroll
    for (int p = 0; p < 4; p++) {
        #pragma unroll
        for (int cc = 0; cc < 4; cc++) {
            int c = (cc + cg) & 3;   // rotated store order (bank spread)
            float2 v = unpack2(acc[p][c]);
            *(u64*)(&sAT[(c0 + c) * SAS + m0 + 2 * p]) =
                pack2(fmaxf(v.x, 0.f), fmaxf(v.y, 0.f));
        }
    }
    __syncthreads();

    // ---- GEMM2: y2 = y1 @ Wi2 + bi2 ----
    #pragma unroll
    for (int c = 0; c < 4; c++) {
        u64 bv = pack2(bi2[c0 + c], bi2[c0 + c]);
        #pragma unroll
        for (int p = 0; p < 4; p++) acc[p][c] = bv;
    }
    #pragma unroll 4
    for (int k = 0; k < 128; k++) {
        GEMM_K_STEP(acc, &sAT[k * SAS + m0], Wi2 + k * 128 + c0);
    }

    // ---- store x_embed + accumulate sumexp over valid hyperedges ----
    const int lenb = g_len[b];
    float4 es = make_float4(0.f, 0.f, 0.f, 0.f);
    bool any = false;
    #pragma unroll
    for (int p = 0; p < 4; p++) {
        const int r0g = row0 + m0 + 2 * p;
        float2 v0 = unpack2(acc[p][0]);
        float2 v1 = unpack2(acc[p][1]);
        float2 v2 = unpack2(acc[p][2]);
        float2 v3 = unpack2(acc[p][3]);
        float4 lo = make_float4(v0.x, v1.x, v2.x, v3.x);   // row r0g
        float4 hi = make_float4(v0.y, v1.y, v2.y, v3.y);   // row r0g+1
        *(float4*)(g_xembed + (size_t)r0g * 128 + c0)       = lo;
        *(float4*)(g_xembed + (size_t)(r0g + 1) * 128 + c0) = hi;
        #pragma unroll
        for (int h = 0; h < 2; h++) {
            const int rem = r0g + h - b * NC;
            const int i  = rem / 1600;
            const int j  = (rem / 40) % 40;
            const int kk = rem % 40;
            if (i < j && j < kk && kk < lenb) {
                float4 v = h ? hi : lo;
                es.x += __expf(v.x);
                es.y += __expf(v.y);
                es.z += __expf(v.z);
                es.w += __expf(v.w);
                any = true;
            }
        }
    }
    if (any) {
        atomicAdd(&sSum[c0 + 0], es.x);
        atomicAdd(&sSum[c0 + 1], es.y);
        atomicAdd(&sSum[c0 + 2], es.z);
        atomicAdd(&sSum[c0 + 3], es.w);
    }
    __syncthreads();
    if (t < 128) {
        float v = sSum[t];
        if (v != 0.f) atomicAdd(&g_sumexp[b * 128 + t], v);
    }
}

// ---------------------------------------------------------------------------
// Kernel 2: out = relu([a * relu(xf@We), xf] @ Wo1 + bo1) @ Wo2 + bo2
// ---------------------------------------------------------------------------
extern __shared__ float smem2[];
__global__ __launch_bounds__(256) void k_out(
    const float* __restrict__ We,
    const float* __restrict__ Wo1, const float* __restrict__ bo1,
    const float* __restrict__ Wo2, const float* __restrict__ bo2,
    float* __restrict__ out)
{
    float* sXFT  = smem2;                  // 128*SAS (transposed xf tile)
    float* sAXIT = smem2 + 128 * SAS;      // 128*SAS (transposed a*x_inner)
    float* sInv  = smem2 + 2 * 128 * SAS;  // 128

    const int row0 = blockIdx.x * 64;
    const int b    = row0 / NC;
    const int t    = threadIdx.x;
    const int cg   = t & 31;
    const int wg   = t >> 5;
    const int c0   = cg * 4;
    const int m0   = wg * 8;

    load_tile_T(g_xembed + (size_t)row0 * 128, sXFT, t);
    if (t < 128) sInv[t] = 1.0f / g_sumexp[b * 128 + t];
    __syncthreads();

    const int lenb = g_len[b];
    bool valid[8];
    bool any = false;
    #pragma unroll
    for (int m = 0; m < 8; m++) {
        const int rem = row0 + m0 + m - b * NC;
        const int i  = rem / 1600;
        const int j  = (rem / 40) % 40;
        const int kk = rem % 40;
        valid[m] = (i < j) && (j < kk) && (kk < lenb);
        any |= valid[m];
    }

    // ---- stage A (valid warps only): axi = a .* relu(xf @ We), transposed ----
    if (any) {
        u64 acc[4][4];
        #pragma unroll
        for (int p = 0; p < 4; p++)
            #pragma unroll
            for (int c = 0; c < 4; c++) acc[p][c] = 0ull;
        #pragma unroll 4
        for (int k = 0; k < 128; k++) {
            GEMM_K_STEP(acc, &sXFT[k * SAS + m0], We + k * 128 + c0);
        }
        float4 inv4 = *(const float4*)(&sInv[c0]);
        const float invc[4] = {inv4.x, inv4.y, inv4.z, inv4.w};
        #pragma unroll
        for (int p = 0; p < 4; p++) {
            const int r0 = m0 + 2 * p;
            const bool v0 = valid[2 * p], v1 = valid[2 * p + 1];
            #pragma unroll
            for (int cc = 0; cc < 4; cc++) {
                int c = (cc + cg) & 3;   // rotated order (bank spread)
                float2 a2 = unpack2(acc[p][c]);
                float xf0 = sXFT[(c0 + c) * SAS + r0];
                float xf1 = sXFT[(c0 + c) * SAS + r0 + 1];
                float o0 = v0 ? __expf(xf0) * invc[c] * fmaxf(a2.x, 0.f) : 0.f;
                float o1 = v1 ? __expf(xf1) * invc[c] * fmaxf(a2.y, 0.f) : 0.f;
                *(u64*)(&sAXIT[(c0 + c) * SAS + r0]) = pack2(o0, o1);
            }
        }
        __syncwarp();
    }

    // ---- stage B: g = relu(h @ Wo1 + bo1); out = g @ Wo2 + bo2 ----
    float rsum[8];
    #pragma unroll
    for (int m = 0; m < 8; m++) rsum[m] = 0.f;

    #pragma unroll
    for (int half = 0; half < 2; half++) {
        const int n0 = half * 128 + c0;
        u64 g[4][4];
        #pragma unroll
        for (int c = 0; c < 4; c++) {
            u64 bv = pack2(bo1[n0 + c], bo1[n0 + c]);
            #pragma unroll
            for (int p = 0; p < 4; p++) g[p][c] = bv;
        }
        // xf part: Wo1 rows 128..255
        #pragma unroll 4
        for (int k = 0; k < 128; k++) {
            GEMM_K_STEP(g, &sXFT[k * SAS + m0], Wo1 + (128 + k) * 256 + n0);
        }
        // a*x_inner part: Wo1 rows 0..127 (skipped when no valid row in warp)
        if (any) {
            #pragma unroll 4
            for (int k = 0; k < 128; k++) {
                GEMM_K_STEP(g, &sAXIT[k * SAS + m0], Wo1 + k * 256 + n0);
            }
        }
        float4 w2v = *(const float4*)(Wo2 + n0);
        #pragma unroll
        for (int p = 0; p < 4; p++) {
            float2 v0 = unpack2(g[p][0]);
            float2 v1 = unpack2(g[p][1]);
            float2 v2 = unpack2(g[p][2]);
            float2 v3 = unpack2(g[p][3]);
            rsum[2 * p]     += fmaxf(v0.x, 0.f) * w2v.x + fmaxf(v1.x, 0.f) * w2v.y
                             + fmaxf(v2.x, 0.f) * w2v.z + fmaxf(v3.x, 0.f) * w2v.w;
            rsum[2 * p + 1] += fmaxf(v0.y, 0.f) * w2v.x + fmaxf(v1.y, 0.f) * w2v.y
                             + fmaxf(v2.y, 0.f) * w2v.z + fmaxf(v3.y, 0.f) * w2v.w;
        }
    }

    #pragma unroll
    for (int off = 16; off; off >>= 1) {
        #pragma unroll
        for (int m = 0; m < 8; m++)
            rsum[m] += __shfl_xor_sync(0xffffffffu, rsum[m], off);
    }
    if (cg == 0) {
        const float b2 = bo2[0];
        #pragma unroll
        for (int m = 0; m < 8; m++)
            out[row0 + m0 + m] = rsum[m] + b2;
    }
}

// ---------------------------------------------------------------------------
extern "C" void kernel_launch(void* const* d_in, const int* in_sizes, int n_in,
                              void* d_out, int out_size) {
    const float* x          = (const float*)d_in[0];
    const unsigned char* mk = (const unsigned char*)d_in[1];
    const float* Wi1        = (const float*)d_in[2];
    const float* bi1        = (const float*)d_in[3];
    const float* Wi2        = (const float*)d_in[4];
    const float* bi2        = (const float*)d_in[5];
    const float* We         = (const float*)d_in[6];
    const float* Wo1        = (const float*)d_in[7];
    const float* bo1        = (const float*)d_in[8];
    const float* Wo2        = (const float*)d_in[9];
    const float* bo2        = (const float*)d_in[10];
    float* out              = (float*)d_out;

    const int smem_k_out = (2 * 128 * SAS + 128) * (int)sizeof(float);  // ~70 KB
    cudaFuncSetAttribute(k_out, cudaFuncAttributeMaxDynamicSharedMemorySize, smem_k_out);

    k_setup<<<1, 512>>>(mk);
    k_embed<<<RT / 64, 256>>>(x, Wi1, bi1, Wi2, bi2);
    k_out<<<RT / 64, 256, smem_k_out>>>(We, Wo1, bo1, Wo2, bo2, out);
}

// round 6
// speedup vs baseline: 2.0661x; 1.3783x over previous
#include <cuda_runtime.h>
#include <cuda_bf16.h>
#include <cstdint>

#define B_   4
#define N_   40
#define NC   64000      // 40^3
#define RT   256000     // B * N^3

typedef unsigned long long u64;

// ---------------- scratch (device globals per allocation rules) ------------
__device__ float g_xembed[(size_t)RT * 128];
__device__ float g_sumexp[B_ * 128];
__device__ int   g_len[B_];
// weight images, [n][k] bf16, stride 136: [0]=W1hi [1]=W1lo [2]=W2hi [3]=W2lo
#define WST 136
__device__ __align__(16) unsigned short g_wT[4][128 * WST];

// ---------------- helpers ---------------------------------------------------
static __device__ __forceinline__ uint32_t smem_u32(const void* p) {
    uint32_t a;
    asm("{ .reg .u64 t; cvta.to.shared.u64 t, %1; cvt.u32.u64 %0, t; }" : "=r"(a) : "l"(p));
    return a;
}
static __device__ __forceinline__ float bfhi(float f) {
    return __bfloat162float(__float2bfloat16(f));
}
static __device__ __forceinline__ uint32_t pack_bf2(float lo, float hi) {
    __nv_bfloat162 h = __floats2bfloat162_rn(lo, hi);   // .x = lo half
    return *reinterpret_cast<uint32_t*>(&h);
}
static __device__ __forceinline__ void ldsm_x4(uint32_t a, uint32_t* r) {
    asm volatile("ldmatrix.sync.aligned.m8n8.x4.shared.b16 {%0,%1,%2,%3}, [%4];"
        : "=r"(r[0]), "=r"(r[1]), "=r"(r[2]), "=r"(r[3]) : "r"(a));
}
static __device__ __forceinline__ void ldsm_x2(uint32_t a, uint32_t* r) {
    asm volatile("ldmatrix.sync.aligned.m8n8.x2.shared.b16 {%0,%1}, [%2];"
        : "=r"(r[0]), "=r"(r[1]) : "r"(a));
}
static __device__ __forceinline__ void mma16816(float* d, const uint32_t* a, const uint32_t* b) {
    asm volatile("mma.sync.aligned.m16n8k16.row.col.f32.bf16.bf16.f32 "
        "{%0,%1,%2,%3}, {%4,%5,%6,%7}, {%8,%9}, {%0,%1,%2,%3};"
        : "+f"(d[0]), "+f"(d[1]), "+f"(d[2]), "+f"(d[3])
        : "r"(a[0]), "r"(a[1]), "r"(a[2]), "r"(a[3]), "r"(b[0]), "r"(b[1]));
}

// ---------------------------------------------------------------------------
// Kernel 0a: mask -> lengths, zero softmax denominators.
// ---------------------------------------------------------------------------
__global__ void k_setup(const unsigned char* __restrict__ mraw) {
    int t = threadIdx.x;
    if (t < B_ * 128) g_sumexp[t] = 0.f;
    if (t < B_) {
        int cnt = 0;
        if (mraw[1] != 0) {
            for (int j = 0; j < N_; j++) cnt += (mraw[t * N_ + j] != 0) ? 1 : 0;
        } else {
            const unsigned int* mi = (const unsigned int*)mraw;
            for (int j = 0; j < N_; j++) cnt += (mi[t * N_ + j] != 0u) ? 1 : 0;
        }
        g_len[t] = cnt;
    }
}

// ---------------------------------------------------------------------------
// Kernel 0b: build transposed bf16 hi/lo weight images [n][k], stride 136.
// ---------------------------------------------------------------------------
__global__ void k_prep(const float* __restrict__ Wi1, const float* __restrict__ Wi2) {
    int idx = blockIdx.x * 256 + threadIdx.x;      // 4 * 128 * 136
    if (idx >= 4 * 128 * WST) return;
    int mat = idx / (128 * WST);
    int r   = idx % (128 * WST);
    int n   = r / WST;
    int k   = r % WST;
    float v = 0.f;
    if (k < 128) {
        v = (mat < 2 ? Wi1 : Wi2)[k * 128 + n];
        if (mat & 1) v = v - bfhi(v);              // lo residual
    }
    __nv_bfloat16 h = __float2bfloat16(v);
    g_wT[mat][n * WST + k] = *reinterpret_cast<unsigned short*>(&h);
}

// ---------------------------------------------------------------------------
// Kernel 1 (HMMA): x_embed = relu(x@Wi1+bi1)@Wi2+bi2, + sumexp. bf16x3 split.
// CTA = 128 rows, 8 warps, each warp M16 x N128.
// ---------------------------------------------------------------------------
#define AHI_OFF 0
#define ALO_OFF 34816
#define W_OFF   69632
#define WIMG    34816
#define SXF_STRIDE 132
#define DSMEM   208896       // 2*34816 (A) + 4*34816 (W); sxf aliases A area

extern __shared__ unsigned char sdyn[];
__global__ __launch_bounds__(256, 1) void k_embed_hmma(
    const float* __restrict__ x,
    const float* __restrict__ bi1, const float* __restrict__ bi2)
{
    __shared__ float s_bias1[128], s_bias2[128];
    __shared__ unsigned char s_vf[128];

    const int t    = threadIdx.x;
    const int lane = t & 31;
    const int w    = t >> 5;
    const int row0 = blockIdx.x * 128;   // 64000 % 128 == 0: no batch straddle
    const int b    = row0 / NC;
    const uint32_t sbase = smem_u32(sdyn);

    // weight images -> smem (linear copy, 139264 B)
    {
        const float4* ws = (const float4*)g_wT;
        float4* wd = (float4*)(sdyn + W_OFF);
        #pragma unroll
        for (int i = 0; i < 34; i++) wd[t + i * 256] = ws[t + i * 256];
    }
    // x tile -> bf16 hi/lo images [row][k], stride 136
    {
        const float4* xg = (const float4*)(x + (size_t)row0 * 128);
        #pragma unroll
        for (int i = 0; i < 16; i++) {
            int fidx = t + i * 256;
            float4 v = xg[fidx];
            int row = fidx >> 5;
            int k   = (fidx & 31) * 4;
            uint32_t hA = pack_bf2(v.x, v.y);
            uint32_t hB = pack_bf2(v.z, v.w);
            uint32_t lA = pack_bf2(v.x - bfhi(v.x), v.y - bfhi(v.y));
            uint32_t lB = pack_bf2(v.z - bfhi(v.z), v.w - bfhi(v.w));
            size_t off = ((size_t)row * WST + k) * 2;
            *(u64*)(sdyn + AHI_OFF + off) = ((u64)hB << 32) | hA;
            *(u64*)(sdyn + ALO_OFF + off) = ((u64)lB << 32) | lA;
        }
    }
    if (t < 128) {
        s_bias1[t] = bi1[t];
        s_bias2[t] = bi2[t];
        const int lenb = g_len[b];
        const int rem = row0 + t - b * NC;
        const int i  = rem / 1600;
        const int j  = (rem / 40) % 40;
        const int kk = rem % 40;
        s_vf[t] = (i < j) && (j < kk) && (kk < lenb);
    }
    __syncthreads();

    const int m0 = w * 16;
    const int c2 = (lane & 3) * 2;
    // ldmatrix lane addressing
    const uint32_t aHi = sbase + AHI_OFF + (((m0 + (lane & 15)) * WST + (lane >> 4) * 8) << 1);
    const uint32_t aLo = aHi + (ALO_OFF - AHI_OFF);
    const uint32_t bAd = sbase + W_OFF + ((((lane & 7) * WST) + ((lane >> 3) & 1) * 8) << 1);

    float acc[16][4];
    #pragma unroll
    for (int nt = 0; nt < 16; nt++)
        acc[nt][0] = acc[nt][1] = acc[nt][2] = acc[nt][3] = 0.f;

    // ---- GEMM1: x @ Wi1 (bf16x3) ----
    #pragma unroll
    for (int ks = 0; ks < 8; ks++) {
        uint32_t ahi[4], alo[4];
        ldsm_x4(aHi + ks * 32, ahi);
        ldsm_x4(aLo + ks * 32, alo);
        #pragma unroll
        for (int nt = 0; nt < 16; nt++) {
            uint32_t bh[2], bl[2];
            ldsm_x2(bAd + 0 * WIMG + nt * (8 * WST * 2) + ks * 32, bh);
            ldsm_x2(bAd + 1 * WIMG + nt * (8 * WST * 2) + ks * 32, bl);
            mma16816(acc[nt], ahi, bh);
            mma16816(acc[nt], ahi, bl);
            mma16816(acc[nt], alo, bh);
        }
    }
    __syncthreads();   // all warps done reading A images (sxf will alias them)

    // ---- epilogue 1 (regs only): y1 = relu(acc + bi1) -> A2 fragments ----
    uint32_t a2h[8][4], a2l[8][4];
    #pragma unroll
    for (int ks = 0; ks < 8; ks++) {
        #pragma unroll
        for (int h = 0; h < 2; h++) {
            const int nt = 2 * ks + h;
            const float b0 = s_bias1[nt * 8 + c2];
            const float b1 = s_bias1[nt * 8 + c2 + 1];
            float f0 = fmaxf(acc[nt][0] + b0, 0.f);
            float f1 = fmaxf(acc[nt][1] + b1, 0.f);
            float f2 = fmaxf(acc[nt][2] + b0, 0.f);
            float f3 = fmaxf(acc[nt][3] + b1, 0.f);
            a2h[ks][0 + 2 * h] = pack_bf2(f0, f1);
            a2h[ks][1 + 2 * h] = pack_bf2(f2, f3);
            a2l[ks][0 + 2 * h] = pack_bf2(f0 - bfhi(f0), f1 - bfhi(f1));
            a2l[ks][1 + 2 * h] = pack_bf2(f2 - bfhi(f2), f3 - bfhi(f3));
        }
    }

    // ---- GEMM2: y1 @ Wi2 (bf16x3), A from registers ----
    #pragma unroll
    for (int nt = 0; nt < 16; nt++)
        acc[nt][0] = acc[nt][1] = acc[nt][2] = acc[nt][3] = 0.f;
    #pragma unroll
    for (int ks = 0; ks < 8; ks++) {
        #pragma unroll
        for (int nt = 0; nt < 16; nt++) {
            uint32_t bh[2], bl[2];
            ldsm_x2(bAd + 2 * WIMG + nt * (8 * WST * 2) + ks * 32, bh);
            ldsm_x2(bAd + 3 * WIMG + nt * (8 * WST * 2) + ks * 32, bl);
            mma16816(acc[nt], a2h[ks], bh);
            mma16816(acc[nt], a2h[ks], bl);
            mma16816(acc[nt], a2l[ks], bh);
        }
    }

    // ---- epilogue 2: xf = acc + bi2 -> smem (stride 132) ----
    float* sxf = (float*)sdyn;           // aliases dead A images
    const int g = lane >> 2;
    #pragma unroll
    for (int nt = 0; nt < 16; nt++) {
        const int nc = nt * 8 + c2;
        const float b0 = s_bias2[nc], b1 = s_bias2[nc + 1];
        *(float2*)(&sxf[(m0 + g) * SXF_STRIDE + nc])     = make_float2(acc[nt][0] + b0, acc[nt][1] + b1);
        *(float2*)(&sxf[(m0 + g + 8) * SXF_STRIDE + nc]) = make_float2(acc[nt][2] + b0, acc[nt][3] + b1);
    }
    __syncthreads();

    // coalesced store of xf
    {
        float4* xo = (float4*)(g_xembed + (size_t)row0 * 128);
        #pragma unroll
        for (int i = 0; i < 16; i++) {
            int idx = t + i * 256;
            int row = idx >> 5;
            int c4  = (idx & 31) * 4;
            const float* p = &sxf[row * SXF_STRIDE + c4];
            xo[idx] = make_float4(p[0], p[1], p[2], p[3]);
        }
    }
    // per-column sumexp over valid rows
    if (t < 128) {
        float s = 0.f;
        for (int r = 0; r < 128; r++)
            if (s_vf[r]) s += __expf(sxf[r * SXF_STRIDE + t]);
        if (s != 0.f) atomicAdd(&g_sumexp[b * 128 + t], s);
    }
}

// ---------------------------------------------------------------------------
// Kernel 2 (round-2 best, unchanged): out = relu([a*relu(xf@We), xf]@Wo1+bo1)@Wo2+bo2
// ---------------------------------------------------------------------------
static __device__ __forceinline__ u64 pk2(float a, float b) {
    u64 r;
    asm("mov.b64 %0, {%1, %2};" : "=l"(r) : "f"(a), "f"(b));
    return r;
}
static __device__ __forceinline__ void ffma2(u64& d, u64 a, u64 b) {
    asm("fma.rn.f32x2 %0, %1, %2, %0;" : "+l"(d) : "l"(a), "l"(b));
}
static __device__ __forceinline__ float2 unpk2(u64 v) {
    float2 f;
    asm("mov.b64 {%0, %1}, %2;" : "=f"(f.x), "=f"(f.y) : "l"(v));
    return f;
}
#define GEMM_STEP_F2(ACC, AV, W0, W1, W2, W3)            \
    do {                                                  \
        u64 _ax = pk2((AV).x, (AV).x);                    \
        u64 _ay = pk2((AV).y, (AV).y);                    \
        u64 _az = pk2((AV).z, (AV).z);                    \
        u64 _aw = pk2((AV).w, (AV).w);                    \
        ffma2((ACC)[0], _ax, (W0).x);                     \
        ffma2((ACC)[1], _ax, (W0).y);                     \
        ffma2((ACC)[0], _ay, (W1).x);                     \
        ffma2((ACC)[1], _ay, (W1).y);                     \
        ffma2((ACC)[0], _az, (W2).x);                     \
        ffma2((ACC)[1], _az, (W2).y);                     \
        ffma2((ACC)[0], _aw, (W3).x);                     \
        ffma2((ACC)[1], _aw, (W3).y);                     \
    } while (0)

extern __shared__ float smem2[];
__global__ __launch_bounds__(256) void k_out(
    const float* __restrict__ We,
    const float* __restrict__ Wo1, const float* __restrict__ bo1,
    const float* __restrict__ Wo2, const float* __restrict__ bo2,
    float* __restrict__ out)
{
    float* sXF  = smem2;
    float* sAXI = smem2 + 64 * 128;
    float* sInv = smem2 + 2 * 64 * 128;

    const int row0 = blockIdx.x * 64;
    const int b    = row0 / NC;
    const int t    = threadIdx.x;
    const int cg   = t & 31;
    const int wg   = t >> 5;
    const int c0   = cg * 4;

    {
        const float4* xg = (const float4*)(g_xembed + (size_t)row0 * 128);
        float4* s4 = (float4*)sXF;
        #pragma unroll
        for (int i = 0; i < 8; i++) s4[t + i * 256] = xg[t + i * 256];
    }
    if (t < 128) sInv[t] = 1.0f / g_sumexp[b * 128 + t];
    __syncthreads();

    const int lenb = g_len[b];
    bool valid[8];
    bool any = false;
    #pragma unroll
    for (int m = 0; m < 8; m++) {
        const int rem = row0 + wg * 8 + m - b * NC;
        const int i  = rem / 1600;
        const int j  = (rem / 40) % 40;
        const int kk = rem % 40;
        valid[m] = (i < j) && (j < kk) && (kk < lenb);
        any |= valid[m];
    }

    if (any) {
        u64 acc[8][2];
        #pragma unroll
        for (int m = 0; m < 8; m++) { acc[m][0] = 0ull; acc[m][1] = 0ull; }
        for (int k = 0; k < 128; k += 4) {
            ulonglong2 w0 = *(const ulonglong2*)(We + (k + 0) * 128 + c0);
            ulonglong2 w1 = *(const ulonglong2*)(We + (k + 1) * 128 + c0);
            ulonglong2 w2 = *(const ulonglong2*)(We + (k + 2) * 128 + c0);
            ulonglong2 w3 = *(const ulonglong2*)(We + (k + 3) * 128 + c0);
            #pragma unroll
            for (int m = 0; m < 8; m++) {
                float4 av = *(const float4*)(&sXF[(wg * 8 + m) * 128 + k]);
                GEMM_STEP_F2(acc[m], av, w0, w1, w2, w3);
            }
        }
        float4 inv4 = *(const float4*)(&sInv[c0]);
        #pragma unroll
        for (int m = 0; m < 8; m++) {
            const int row = wg * 8 + m;
            float4 v = make_float4(0.f, 0.f, 0.f, 0.f);
            if (valid[m]) {
                float4 xfv = *(const float4*)(&sXF[row * 128 + c0]);
                float2 lo = unpk2(acc[m][0]);
                float2 hi = unpk2(acc[m][1]);
                v.x = __expf(xfv.x) * inv4.x * fmaxf(lo.x, 0.f);
                v.y = __expf(xfv.y) * inv4.y * fmaxf(lo.y, 0.f);
                v.z = __expf(xfv.z) * inv4.z * fmaxf(hi.x, 0.f);
                v.w = __expf(xfv.w) * inv4.w * fmaxf(hi.y, 0.f);
            }
            *(float4*)(&sAXI[row * 128 + c0]) = v;
        }
        __syncwarp();
    }

    float rsum[8];
    #pragma unroll
    for (int m = 0; m < 8; m++) rsum[m] = 0.f;

    #pragma unroll
    for (int half = 0; half < 2; half++) {
        const int n0 = half * 128 + c0;
        u64 g[8][2];
        {
            ulonglong2 bias = *(const ulonglong2*)(bo1 + n0);
            #pragma unroll
            for (int m = 0; m < 8; m++) { g[m][0] = bias.x; g[m][1] = bias.y; }
        }
        for (int k = 0; k < 128; k += 4) {
            ulonglong2 w0 = *(const ulonglong2*)(Wo1 + (128 + k + 0) * 256 + n0);
            ulonglong2 w1 = *(const ulonglong2*)(Wo1 + (128 + k + 1) * 256 + n0);
            ulonglong2 w2 = *(const ulonglong2*)(Wo1 + (128 + k + 2) * 256 + n0);
            ulonglong2 w3 = *(const ulonglong2*)(Wo1 + (128 + k + 3) * 256 + n0);
            #pragma unroll
            for (int m = 0; m < 8; m++) {
                float4 av = *(const float4*)(&sXF[(wg * 8 + m) * 128 + k]);
                GEMM_STEP_F2(g[m], av, w0, w1, w2, w3);
            }
        }
        if (any) {
            for (int k = 0; k < 128; k += 4) {
                ulonglong2 w0 = *(const ulonglong2*)(Wo1 + (k + 0) * 256 + n0);
                ulonglong2 w1 = *(const ulonglong2*)(Wo1 + (k + 1) * 256 + n0);
                ulonglong2 w2 = *(const ulonglong2*)(Wo1 + (k + 2) * 256 + n0);
                ulonglong2 w3 = *(const ulonglong2*)(Wo1 + (k + 3) * 256 + n0);
                #pragma unroll
                for (int m = 0; m < 8; m++) {
                    float4 av = *(const float4*)(&sAXI[(wg * 8 + m) * 128 + k]);
                    GEMM_STEP_F2(g[m], av, w0, w1, w2, w3);
                }
            }
        }
        float4 w2v = *(const float4*)(Wo2 + n0);
        #pragma unroll
        for (int m = 0; m < 8; m++) {
            float2 lo = unpk2(g[m][0]);
            float2 hi = unpk2(g[m][1]);
            rsum[m] += fmaxf(lo.x, 0.f) * w2v.x + fmaxf(lo.y, 0.f) * w2v.y
                     + fmaxf(hi.x, 0.f) * w2v.z + fmaxf(hi.y, 0.f) * w2v.w;
        }
    }

    #pragma unroll
    for (int off = 16; off; off >>= 1) {
        #pragma unroll
        for (int m = 0; m < 8; m++)
            rsum[m] += __shfl_xor_sync(0xffffffffu, rsum[m], off);
    }
    if (cg == 0) {
        const float b2 = bo2[0];
        #pragma unroll
        for (int m = 0; m < 8; m++)
            out[row0 + wg * 8 + m] = rsum[m] + b2;
    }
}

// ---------------------------------------------------------------------------
extern "C" void kernel_launch(void* const* d_in, const int* in_sizes, int n_in,
                              void* d_out, int out_size) {
    const float* x          = (const float*)d_in[0];
    const unsigned char* mk = (const unsigned char*)d_in[1];
    const float* Wi1        = (const float*)d_in[2];
    const float* bi1        = (const float*)d_in[3];
    const float* Wi2        = (const float*)d_in[4];
    const float* bi2        = (const float*)d_in[5];
    const float* We         = (const float*)d_in[6];
    const float* Wo1        = (const float*)d_in[7];
    const float* bo1        = (const float*)d_in[8];
    const float* Wo2        = (const float*)d_in[9];
    const float* bo2        = (const float*)d_in[10];
    float* out              = (float*)d_out;

    const int smem_k_out = (2 * 64 * 128 + 128) * (int)sizeof(float);
    cudaFuncSetAttribute(k_embed_hmma, cudaFuncAttributeMaxDynamicSharedMemorySize, DSMEM);
    cudaFuncSetAttribute(k_out, cudaFuncAttributeMaxDynamicSharedMemorySize, smem_k_out);

    k_setup<<<1, 512>>>(mk);
    k_prep<<<(4 * 128 * WST + 255) / 256, 256>>>(Wi1, Wi2);
    k_embed_hmma<<<RT / 128, 256, DSMEM>>>(x, bi1, bi2);
    k_out<<<RT / 64, 256, smem_k_out>>>(We, Wo1, bo1, Wo2, bo2, out);
}

// round 7
// speedup vs baseline: 2.4803x; 1.2005x over previous
#include <cuda_runtime.h>
#include <cuda_bf16.h>
#include <cstdint>

#define B_   4
#define N_   40
#define NC   64000      // 40^3
#define RT   256000     // B * N^3
#define WST  136

typedef unsigned long long u64;

// ---------------- scratch (device globals per allocation rules) ------------
__device__ float g_xembed[(size_t)RT * 128];
__device__ float g_sumexp[B_ * 128];
__device__ int   g_len[B_];
__device__ __align__(16) unsigned short g_wT[4][128 * WST];     // Wi1/Wi2 hi,lo [n][k]
__device__ __align__(16) unsigned short g_weT[2][128 * WST];    // We hi,lo [n][k]
__device__ __align__(16) unsigned short g_wo1T[2][256 * 256];   // Wo1 hi,lo [n][k]

// ---------------- helpers ---------------------------------------------------
static __device__ __forceinline__ uint32_t smem_u32(const void* p) {
    uint32_t a;
    asm("{ .reg .u64 t; cvta.to.shared.u64 t, %1; cvt.u32.u64 %0, t; }" : "=r"(a) : "l"(p));
    return a;
}
static __device__ __forceinline__ float bfhi(float f) {
    return __bfloat162float(__float2bfloat16(f));
}
static __device__ __forceinline__ uint32_t pack_bf2(float lo, float hi) {
    __nv_bfloat162 h = __floats2bfloat162_rn(lo, hi);
    return *reinterpret_cast<uint32_t*>(&h);
}
static __device__ __forceinline__ void ldsm_x4(uint32_t a, uint32_t* r) {
    asm volatile("ldmatrix.sync.aligned.m8n8.x4.shared.b16 {%0,%1,%2,%3}, [%4];"
        : "=r"(r[0]), "=r"(r[1]), "=r"(r[2]), "=r"(r[3]) : "r"(a));
}
static __device__ __forceinline__ void ldsm_x2(uint32_t a, uint32_t* r) {
    asm volatile("ldmatrix.sync.aligned.m8n8.x2.shared.b16 {%0,%1}, [%2];"
        : "=r"(r[0]), "=r"(r[1]) : "r"(a));
}
static __device__ __forceinline__ void mma16816(float* d, const uint32_t* a, const uint32_t* b) {
    asm volatile("mma.sync.aligned.m16n8k16.row.col.f32.bf16.bf16.f32 "
        "{%0,%1,%2,%3}, {%4,%5,%6,%7}, {%8,%9}, {%0,%1,%2,%3};"
        : "+f"(d[0]), "+f"(d[1]), "+f"(d[2]), "+f"(d[3])
        : "r"(a[0]), "r"(a[1]), "r"(a[2]), "r"(a[3]), "r"(b[0]), "r"(b[1]));
}

// ---------------------------------------------------------------------------
// Kernel 0a: mask -> lengths, zero softmax denominators.
// ---------------------------------------------------------------------------
__global__ void k_setup(const unsigned char* __restrict__ mraw) {
    int t = threadIdx.x;
    if (t < B_ * 128) g_sumexp[t] = 0.f;
    if (t < B_) {
        int cnt = 0;
        if (mraw[1] != 0) {
            for (int j = 0; j < N_; j++) cnt += (mraw[t * N_ + j] != 0) ? 1 : 0;
        } else {
            const unsigned int* mi = (const unsigned int*)mraw;
            for (int j = 0; j < N_; j++) cnt += (mi[t * N_ + j] != 0u) ? 1 : 0;
        }
        g_len[t] = cnt;
    }
}

// ---------------------------------------------------------------------------
// Kernel 0b: transposed bf16 hi/lo weight images for Wi1, Wi2, We, Wo1.
// ---------------------------------------------------------------------------
__global__ void k_prep(const float* __restrict__ Wi1, const float* __restrict__ Wi2,
                       const float* __restrict__ We,  const float* __restrict__ Wo1) {
    int idx = blockIdx.x * 256 + threadIdx.x;
    if (idx < 4 * 128 * WST) {
        int mat = idx / (128 * WST);
        int r   = idx % (128 * WST);
        int n   = r / WST;
        int k   = r % WST;
        float v = 0.f;
        if (k < 128) {
            v = (mat < 2 ? Wi1 : Wi2)[k * 128 + n];
            if (mat & 1) v = v - bfhi(v);
        }
        __nv_bfloat16 h = __float2bfloat16(v);
        g_wT[mat][n * WST + k] = *reinterpret_cast<unsigned short*>(&h);
    } else if (idx < 6 * 128 * WST) {
        int r   = idx - 4 * 128 * WST;
        int img = r / (128 * WST);
        int rr  = r % (128 * WST);
        int n   = rr / WST;
        int k   = rr % WST;
        float v = 0.f;
        if (k < 128) {
            v = We[k * 128 + n];
            if (img) v = v - bfhi(v);
        }
        __nv_bfloat16 h = __float2bfloat16(v);
        g_weT[img][n * WST + k] = *reinterpret_cast<unsigned short*>(&h);
    } else if (idx < 6 * 128 * WST + 2 * 65536) {
        int r   = idx - 6 * 128 * WST;
        int img = r / 65536;
        int rr  = r % 65536;
        int n   = rr / 256;
        int k   = rr % 256;
        float v = Wo1[k * 256 + n];
        if (img) v = v - bfhi(v);
        __nv_bfloat16 h = __float2bfloat16(v);
        g_wo1T[img][n * 256 + k] = *reinterpret_cast<unsigned short*>(&h);
    }
}

// ---------------------------------------------------------------------------
// Kernel 1 (HMMA, unchanged from round 6): x_embed + sumexp.
// ---------------------------------------------------------------------------
#define AHI_OFF 0
#define ALO_OFF 34816
#define W_OFF   69632
#define WIMG    34816
#define SXF_STRIDE 132
#define DSMEM   208896

extern __shared__ unsigned char sdyn[];
__global__ __launch_bounds__(256, 1) void k_embed_hmma(
    const float* __restrict__ x,
    const float* __restrict__ bi1, const float* __restrict__ bi2)
{
    __shared__ float s_bias1[128], s_bias2[128];
    __shared__ unsigned char s_vf[128];

    const int t    = threadIdx.x;
    const int lane = t & 31;
    const int w    = t >> 5;
    const int row0 = blockIdx.x * 128;
    const int b    = row0 / NC;
    const uint32_t sbase = smem_u32(sdyn);

    {
        const float4* ws = (const float4*)g_wT;
        float4* wd = (float4*)(sdyn + W_OFF);
        #pragma unroll
        for (int i = 0; i < 34; i++) wd[t + i * 256] = ws[t + i * 256];
    }
    {
        const float4* xg = (const float4*)(x + (size_t)row0 * 128);
        #pragma unroll
        for (int i = 0; i < 16; i++) {
            int fidx = t + i * 256;
            float4 v = xg[fidx];
            int row = fidx >> 5;
            int k   = (fidx & 31) * 4;
            uint32_t hA = pack_bf2(v.x, v.y);
            uint32_t hB = pack_bf2(v.z, v.w);
            uint32_t lA = pack_bf2(v.x - bfhi(v.x), v.y - bfhi(v.y));
            uint32_t lB = pack_bf2(v.z - bfhi(v.z), v.w - bfhi(v.w));
            size_t off = ((size_t)row * WST + k) * 2;
            *(u64*)(sdyn + AHI_OFF + off) = ((u64)hB << 32) | hA;
            *(u64*)(sdyn + ALO_OFF + off) = ((u64)lB << 32) | lA;
        }
    }
    if (t < 128) {
        s_bias1[t] = bi1[t];
        s_bias2[t] = bi2[t];
        const int lenb = g_len[b];
        const int rem = row0 + t - b * NC;
        const int i  = rem / 1600;
        const int j  = (rem / 40) % 40;
        const int kk = rem % 40;
        s_vf[t] = (i < j) && (j < kk) && (kk < lenb);
    }
    __syncthreads();

    const int m0 = w * 16;
    const int c2 = (lane & 3) * 2;
    const uint32_t aHi = sbase + AHI_OFF + (((m0 + (lane & 15)) * WST + (lane >> 4) * 8) << 1);
    const uint32_t aLo = aHi + (ALO_OFF - AHI_OFF);
    const uint32_t bAd = sbase + W_OFF + ((((lane & 7) * WST) + ((lane >> 3) & 1) * 8) << 1);

    float acc[16][4];
    #pragma unroll
    for (int nt = 0; nt < 16; nt++)
        acc[nt][0] = acc[nt][1] = acc[nt][2] = acc[nt][3] = 0.f;

    #pragma unroll
    for (int ks = 0; ks < 8; ks++) {
        uint32_t ahi[4], alo[4];
        ldsm_x4(aHi + ks * 32, ahi);
        ldsm_x4(aLo + ks * 32, alo);
        #pragma unroll
        for (int nt = 0; nt < 16; nt++) {
            uint32_t bh[2], bl[2];
            ldsm_x2(bAd + 0 * WIMG + nt * (8 * WST * 2) + ks * 32, bh);
            ldsm_x2(bAd + 1 * WIMG + nt * (8 * WST * 2) + ks * 32, bl);
            mma16816(acc[nt], ahi, bh);
            mma16816(acc[nt], ahi, bl);
            mma16816(acc[nt], alo, bh);
        }
    }
    __syncthreads();

    uint32_t a2h[8][4], a2l[8][4];
    #pragma unroll
    for (int ks = 0; ks < 8; ks++) {
        #pragma unroll
        for (int h = 0; h < 2; h++) {
            const int nt = 2 * ks + h;
            const float b0 = s_bias1[nt * 8 + c2];
            const float b1 = s_bias1[nt * 8 + c2 + 1];
            float f0 = fmaxf(acc[nt][0] + b0, 0.f);
            float f1 = fmaxf(acc[nt][1] + b1, 0.f);
            float f2 = fmaxf(acc[nt][2] + b0, 0.f);
            float f3 = fmaxf(acc[nt][3] + b1, 0.f);
            a2h[ks][0 + 2 * h] = pack_bf2(f0, f1);
            a2h[ks][1 + 2 * h] = pack_bf2(f2, f3);
            a2l[ks][0 + 2 * h] = pack_bf2(f0 - bfhi(f0), f1 - bfhi(f1));
            a2l[ks][1 + 2 * h] = pack_bf2(f2 - bfhi(f2), f3 - bfhi(f3));
        }
    }

    #pragma unroll
    for (int nt = 0; nt < 16; nt++)
        acc[nt][0] = acc[nt][1] = acc[nt][2] = acc[nt][3] = 0.f;
    #pragma unroll
    for (int ks = 0; ks < 8; ks++) {
        #pragma unroll
        for (int nt = 0; nt < 16; nt++) {
            uint32_t bh[2], bl[2];
            ldsm_x2(bAd + 2 * WIMG + nt * (8 * WST * 2) + ks * 32, bh);
            ldsm_x2(bAd + 3 * WIMG + nt * (8 * WST * 2) + ks * 32, bl);
            mma16816(acc[nt], a2h[ks], bh);
            mma16816(acc[nt], a2h[ks], bl);
            mma16816(acc[nt], a2l[ks], bh);
        }
    }

    float* sxf = (float*)sdyn;
    const int g = lane >> 2;
    #pragma unroll
    for (int nt = 0; nt < 16; nt++) {
        const int nc = nt * 8 + c2;
        const float b0 = s_bias2[nc], b1 = s_bias2[nc + 1];
        *(float2*)(&sxf[(m0 + g) * SXF_STRIDE + nc])     = make_float2(acc[nt][0] + b0, acc[nt][1] + b1);
        *(float2*)(&sxf[(m0 + g + 8) * SXF_STRIDE + nc]) = make_float2(acc[nt][2] + b0, acc[nt][3] + b1);
    }
    __syncthreads();

    {
        float4* xo = (float4*)(g_xembed + (size_t)row0 * 128);
        #pragma unroll
        for (int i = 0; i < 16; i++) {
            int idx = t + i * 256;
            int row = idx >> 5;
            int c4  = (idx & 31) * 4;
            const float* p = &sxf[row * SXF_STRIDE + c4];
            xo[idx] = make_float4(p[0], p[1], p[2], p[3]);
        }
    }
    if (t < 128) {
        float s = 0.f;
        for (int r = 0; r < 128; r++)
            if (s_vf[r]) s += __expf(sxf[r * SXF_STRIDE + t]);
        if (s != 0.f) atomicAdd(&g_sumexp[b * 128 + t], s);
    }
}

// ---------------------------------------------------------------------------
// Kernel 2 (HMMA): out = relu([a*relu(xf@We), xf]@Wo1+bo1)@Wo2+bo2
// 128-row tiles, 8 warps. Phase 1: xf/axi/We images. Phase 2: smem reused as
// Wo1 half-buffers (A fragments live in registers).
// ---------------------------------------------------------------------------
#define XFHI 0
#define XFLO 34816
#define AXHI 69632
#define AXLO 104448
#define WEHI 139264
#define WELO 174080
#define WO1LO_OFF 67584          // phase-2: hi at 0 (stride 264), lo at 67584

__global__ __launch_bounds__(256, 1) void k_out_hmma(
    const float* __restrict__ bo1,
    const float* __restrict__ Wo2, const float* __restrict__ bo2,
    float* __restrict__ out)
{
    __shared__ float s_bo1[256], s_wo2[256], s_inv[128];
    __shared__ unsigned char s_vf[128];

    const int t    = threadIdx.x;
    const int lane = t & 31;
    const int w    = t >> 5;
    const int row0 = blockIdx.x * 128;
    const int b    = row0 / NC;
    const uint32_t sbase = smem_u32(sdyn);

    // ---- preamble: flags, biases ----
    if (t < 128) {
        s_inv[t] = 1.0f / g_sumexp[b * 128 + t];
        const int lenb = g_len[b];
        const int rem = row0 + t - b * NC;
        const int i  = rem / 1600;
        const int j  = (rem / 40) % 40;
        const int kk = rem % 40;
        s_vf[t] = (i < j) && (j < kk) && (kk < lenb);
    }
    s_bo1[t] = bo1[t];
    s_bo1[t + ((t < 0) ? 0 : 0)] = bo1[t];   // no-op keep
    if (t < 256) { s_wo2[t] = Wo2[t]; }
    const int bany = __syncthreads_or((t < 128) ? (int)s_vf[t] : 0);

    // ---- xf tile -> bf16 hi/lo images ----
    {
        const float4* xg = (const float4*)(g_xembed + (size_t)row0 * 128);
        #pragma unroll
        for (int i = 0; i < 16; i++) {
            int fidx = t + i * 256;
            float4 v = xg[fidx];
            int row = fidx >> 5;
            int k   = (fidx & 31) * 4;
            uint32_t hA = pack_bf2(v.x, v.y);
            uint32_t hB = pack_bf2(v.z, v.w);
            uint32_t lA = pack_bf2(v.x - bfhi(v.x), v.y - bfhi(v.y));
            uint32_t lB = pack_bf2(v.z - bfhi(v.z), v.w - bfhi(v.w));
            size_t off = ((size_t)row * WST + k) * 2;
            *(u64*)(sdyn + XFHI + off) = ((u64)hB << 32) | hA;
            *(u64*)(sdyn + XFLO + off) = ((u64)lB << 32) | lA;
        }
    }
    // We images (only needed when the block has valid rows)
    if (bany) {
        const float4* ws = (const float4*)g_weT;
        float4* wd = (float4*)(sdyn + WEHI);
        #pragma unroll
        for (int i = 0; i < 17; i++) wd[t + i * 256] = ws[t + i * 256];
    }
    __syncthreads();

    const int m0 = w * 16;
    const int c2 = (lane & 3) * 2;
    const int g  = lane >> 2;
    const uint32_t aAddr = sbase + (((m0 + (lane & 15)) * WST + (lane >> 4) * 8) << 1);
    const uint32_t bAddr136 = sbase + ((((lane & 7) * WST) + ((lane >> 3) & 1) * 8) << 1);

    // ---- xf A-fragments -> registers ----
    uint32_t xfh[8][4], xfl[8][4];
    #pragma unroll
    for (int ks = 0; ks < 8; ks++) {
        ldsm_x4(aAddr + XFHI + ks * 32, xfh[ks]);
        ldsm_x4(aAddr + XFLO + ks * 32, xfl[ks]);
    }

    // ---- stage A: axi = a .* relu(xf @ We) (per-warp skip) ----
    const int vlane = s_vf[m0 + (lane & 15)];
    const int warp_any = __any_sync(0xffffffffu, vlane);
    uint32_t axh[8][4], axl[8][4];
    if (warp_any) {
        const int r0 = m0 + g, r1 = m0 + g + 8;
        const bool v0 = s_vf[r0], v1 = s_vf[r1];
        #pragma unroll
        for (int nt = 0; nt < 16; nt++) {
            float acc[4] = {0.f, 0.f, 0.f, 0.f};
            #pragma unroll
            for (int ks = 0; ks < 8; ks++) {
                uint32_t bh[2], bl[2];
                ldsm_x2(bAddr136 + WEHI + nt * (8 * WST * 2) + ks * 32, bh);
                ldsm_x2(bAddr136 + WELO + nt * (8 * WST * 2) + ks * 32, bl);
                mma16816(acc, xfh[ks], bh);
                mma16816(acc, xfh[ks], bl);
                mma16816(acc, xfl[ks], bh);
            }
            const int c = nt * 8 + c2;
            const float i0 = s_inv[c], i1 = s_inv[c + 1];
            // reconstruct xf from hi+lo images for the softmax numerator
            float v00 = 0.f, v01 = 0.f, v10 = 0.f, v11 = 0.f;
            if (v0) {
                __nv_bfloat162 h = *(__nv_bfloat162*)(sdyn + XFHI + ((r0 * WST + c) << 1));
                __nv_bfloat162 l = *(__nv_bfloat162*)(sdyn + XFLO + ((r0 * WST + c) << 1));
                float x0 = __bfloat162float(h.x) + __bfloat162float(l.x);
                float x1 = __bfloat162float(h.y) + __bfloat162float(l.y);
                v00 = __expf(x0) * i0 * fmaxf(acc[0], 0.f);
                v01 = __expf(x1) * i1 * fmaxf(acc[1], 0.f);
            }
            if (v1) {
                __nv_bfloat162 h = *(__nv_bfloat162*)(sdyn + XFHI + ((r1 * WST + c) << 1));
                __nv_bfloat162 l = *(__nv_bfloat162*)(sdyn + XFLO + ((r1 * WST + c) << 1));
                float x0 = __bfloat162float(h.x) + __bfloat162float(l.x);
                float x1 = __bfloat162float(h.y) + __bfloat162float(l.y);
                v10 = __expf(x0) * i0 * fmaxf(acc[2], 0.f);
                v11 = __expf(x1) * i1 * fmaxf(acc[3], 0.f);
            }
            *(uint32_t*)(sdyn + AXHI + ((r0 * WST + c) << 1)) = pack_bf2(v00, v01);
            *(uint32_t*)(sdyn + AXLO + ((r0 * WST + c) << 1)) = pack_bf2(v00 - bfhi(v00), v01 - bfhi(v01));
            *(uint32_t*)(sdyn + AXHI + ((r1 * WST + c) << 1)) = pack_bf2(v10, v11);
            *(uint32_t*)(sdyn + AXLO + ((r1 * WST + c) << 1)) = pack_bf2(v10 - bfhi(v10), v11 - bfhi(v11));
        }
        __syncwarp();
        #pragma unroll
        for (int ks = 0; ks < 8; ks++) {
            ldsm_x4(aAddr + AXHI + ks * 32, axh[ks]);
            ldsm_x4(aAddr + AXLO + ks * 32, axl[ks]);
        }
    }

    // ---- stage B: loop over two 128-col halves of Wo1 ----
    float rsum0 = 0.f, rsum1 = 0.f;
    const uint32_t bAddr264 = sbase + ((((lane & 7) * 264) + ((lane >> 3) & 1) * 8) << 1);

    #pragma unroll
    for (int half = 0; half < 2; half++) {
        __syncthreads();   // previous phase-1 / previous half reads complete
        // cooperative copy Wo1T[half] hi/lo -> smem (stride 264)
        #pragma unroll
        for (int img = 0; img < 2; img++) {
            const uint4* src = (const uint4*)(g_wo1T[img] + (half * 128) * 256);
            #pragma unroll
            for (int i = 0; i < 16; i++) {
                int e = t + i * 256;
                int r = e >> 5;
                int kq = (e & 31) * 8;
                *(uint4*)(sdyn + img * WO1LO_OFF + ((r * 264 + kq) << 1)) = src[e];
            }
        }
        __syncthreads();

        #pragma unroll
        for (int nt = 0; nt < 16; nt++) {
            float acc[4] = {0.f, 0.f, 0.f, 0.f};
            #pragma unroll
            for (int ks = 0; ks < 8; ks++) {
                uint32_t bh[2], bl[2];
                // xf part: Wo1 rows k = 128 + ks*16
                ldsm_x2(bAddr264 + nt * (8 * 264 * 2) + (128 + ks * 16) * 2, bh);
                ldsm_x2(bAddr264 + WO1LO_OFF + nt * (8 * 264 * 2) + (128 + ks * 16) * 2, bl);
                mma16816(acc, xfh[ks], bh);
                mma16816(acc, xfh[ks], bl);
                mma16816(acc, xfl[ks], bh);
                if (warp_any) {
                    uint32_t bh2[2], bl2[2];
                    ldsm_x2(bAddr264 + nt * (8 * 264 * 2) + (ks * 16) * 2, bh2);
                    ldsm_x2(bAddr264 + WO1LO_OFF + nt * (8 * 264 * 2) + (ks * 16) * 2, bl2);
                    mma16816(acc, axh[ks], bh2);
                    mma16816(acc, axh[ks], bl2);
                    mma16816(acc, axl[ks], bh2);
                }
            }
            const int col = half * 128 + nt * 8 + c2;
            const float g0 = fmaxf(acc[0] + s_bo1[col],     0.f);
            const float g1 = fmaxf(acc[1] + s_bo1[col + 1], 0.f);
            const float g2 = fmaxf(acc[2] + s_bo1[col],     0.f);
            const float g3 = fmaxf(acc[3] + s_bo1[col + 1], 0.f);
            rsum0 += g0 * s_wo2[col] + g1 * s_wo2[col + 1];
            rsum1 += g2 * s_wo2[col] + g3 * s_wo2[col + 1];
        }
    }

    // reduce over the 4 column-lanes of each row group
    rsum0 += __shfl_xor_sync(0xffffffffu, rsum0, 1);
    rsum0 += __shfl_xor_sync(0xffffffffu, rsum0, 2);
    rsum1 += __shfl_xor_sync(0xffffffffu, rsum1, 1);
    rsum1 += __shfl_xor_sync(0xffffffffu, rsum1, 2);
    if ((lane & 3) == 0) {
        const float b2 = bo2[0];
        out[row0 + m0 + g]     = rsum0 + b2;
        out[row0 + m0 + g + 8] = rsum1 + b2;
    }
}

// ---------------------------------------------------------------------------
extern "C" void kernel_launch(void* const* d_in, const int* in_sizes, int n_in,
                              void* d_out, int out_size) {
    const float* x          = (const float*)d_in[0];
    const unsigned char* mk = (const unsigned char*)d_in[1];
    const float* Wi1        = (const float*)d_in[2];
    const float* bi1        = (const float*)d_in[3];
    const float* Wi2        = (const float*)d_in[4];
    const float* bi2        = (const float*)d_in[5];
    const float* We         = (const float*)d_in[6];
    const float* Wo1        = (const float*)d_in[7];
    const float* bo1        = (const float*)d_in[8];
    const float* Wo2        = (const float*)d_in[9];
    const float* bo2        = (const float*)d_in[10];
    float* out              = (float*)d_out;

    cudaFuncSetAttribute(k_embed_hmma, cudaFuncAttributeMaxDynamicSharedMemorySize, DSMEM);
    cudaFuncSetAttribute(k_out_hmma, cudaFuncAttributeMaxDynamicSharedMemorySize, DSMEM);

    const int prep_elems = 6 * 128 * WST + 2 * 65536;
    k_setup<<<1, 512>>>(mk);
    k_prep<<<(prep_elems + 255) / 256, 256>>>(Wi1, Wi2, We, Wo1);
    k_embed_hmma<<<RT / 128, 256, DSMEM>>>(x, bi1, bi2);
    k_out_hmma<<<RT / 128, 256, DSMEM>>>(bo1, Wo2, bo2, out);
}

// round 8
// speedup vs baseline: 3.1538x; 1.2715x over previous
#include <cuda_runtime.h>
#include <cuda_bf16.h>
#include <cstdint>

#define B_   4
#define N_   40
#define NC   64000      // 40^3
#define RT   256000     // B * N^3
#define WST  136

typedef unsigned long long u64;

// ---------------- scratch (device globals per allocation rules) ------------
__device__ float g_xembed[(size_t)RT * 128];
__device__ float g_sumexp[B_ * 128];
__device__ int   g_len[B_];
__device__ __align__(16) unsigned short g_wT[4][128 * WST];     // Wi1/Wi2 hi,lo [n][k]
__device__ __align__(16) unsigned short g_weT[2][128 * WST];    // We hi,lo [n][k]
__device__ __align__(16) unsigned short g_wo1T[2][256 * 256];   // Wo1 hi,lo [n][k]

// ---------------- helpers ---------------------------------------------------
static __device__ __forceinline__ uint32_t smem_u32(const void* p) {
    uint32_t a;
    asm("{ .reg .u64 t; cvta.to.shared.u64 t, %1; cvt.u32.u64 %0, t; }" : "=r"(a) : "l"(p));
    return a;
}
static __device__ __forceinline__ float bfhi(float f) {
    return __bfloat162float(__float2bfloat16(f));
}
static __device__ __forceinline__ uint32_t pack_bf2(float lo, float hi) {
    __nv_bfloat162 h = __floats2bfloat162_rn(lo, hi);
    return *reinterpret_cast<uint32_t*>(&h);
}
static __device__ __forceinline__ void ldsm_x4(uint32_t a, uint32_t* r) {
    asm volatile("ldmatrix.sync.aligned.m8n8.x4.shared.b16 {%0,%1,%2,%3}, [%4];"
        : "=r"(r[0]), "=r"(r[1]), "=r"(r[2]), "=r"(r[3]) : "r"(a));
}
static __device__ __forceinline__ void mma16816(float* d, const uint32_t* a, const uint32_t* b) {
    asm volatile("mma.sync.aligned.m16n8k16.row.col.f32.bf16.bf16.f32 "
        "{%0,%1,%2,%3}, {%4,%5,%6,%7}, {%8,%9}, {%0,%1,%2,%3};"
        : "+f"(d[0]), "+f"(d[1]), "+f"(d[2]), "+f"(d[3])
        : "r"(a[0]), "r"(a[1]), "r"(a[2]), "r"(a[3]), "r"(b[0]), "r"(b[1]));
}

// ---------------------------------------------------------------------------
// Kernel 0a: mask -> lengths, zero softmax denominators.
// ---------------------------------------------------------------------------
__global__ void k_setup(const unsigned char* __restrict__ mraw) {
    int t = threadIdx.x;
    if (t < B_ * 128) g_sumexp[t] = 0.f;
    if (t < B_) {
        int cnt = 0;
        if (mraw[1] != 0) {
            for (int j = 0; j < N_; j++) cnt += (mraw[t * N_ + j] != 0) ? 1 : 0;
        } else {
            const unsigned int* mi = (const unsigned int*)mraw;
            for (int j = 0; j < N_; j++) cnt += (mi[t * N_ + j] != 0u) ? 1 : 0;
        }
        g_len[t] = cnt;
    }
}

// ---------------------------------------------------------------------------
// Kernel 0b: transposed bf16 hi/lo weight images for Wi1, Wi2, We, Wo1.
// ---------------------------------------------------------------------------
__global__ void k_prep(const float* __restrict__ Wi1, const float* __restrict__ Wi2,
                       const float* __restrict__ We,  const float* __restrict__ Wo1) {
    int idx = blockIdx.x * 256 + threadIdx.x;
    if (idx < 4 * 128 * WST) {
        int mat = idx / (128 * WST);
        int r   = idx % (128 * WST);
        int n   = r / WST;
        int k   = r % WST;
        float v = 0.f;
        if (k < 128) {
            v = (mat < 2 ? Wi1 : Wi2)[k * 128 + n];
            if (mat & 1) v = v - bfhi(v);
        }
        __nv_bfloat16 h = __float2bfloat16(v);
        g_wT[mat][n * WST + k] = *reinterpret_cast<unsigned short*>(&h);
    } else if (idx < 6 * 128 * WST) {
        int r   = idx - 4 * 128 * WST;
        int img = r / (128 * WST);
        int rr  = r % (128 * WST);
        int n   = rr / WST;
        int k   = rr % WST;
        float v = 0.f;
        if (k < 128) {
            v = We[k * 128 + n];
            if (img) v = v - bfhi(v);
        }
        __nv_bfloat16 h = __float2bfloat16(v);
        g_weT[img][n * WST + k] = *reinterpret_cast<unsigned short*>(&h);
    } else if (idx < 6 * 128 * WST + 2 * 65536) {
        int r   = idx - 6 * 128 * WST;
        int img = r / 65536;
        int rr  = r % 65536;
        int n   = rr / 256;
        int k   = rr % 256;
        float v = Wo1[k * 256 + n];
        if (img) v = v - bfhi(v);
        __nv_bfloat16 h = __float2bfloat16(v);
        g_wo1T[img][n * 256 + k] = *reinterpret_cast<unsigned short*>(&h);
    }
}

// ---------------------------------------------------------------------------
// Kernel 1 (HMMA): x_embed + sumexp. B loads now paired via ldmatrix.x4.
// ---------------------------------------------------------------------------
#define AHI_OFF 0
#define ALO_OFF 34816
#define W_OFF   69632
#define WIMG    34816
#define SXF_STRIDE 132
#define DSMEM   208896

extern __shared__ unsigned char sdyn[];
__global__ __launch_bounds__(256, 1) void k_embed_hmma(
    const float* __restrict__ x,
    const float* __restrict__ bi1, const float* __restrict__ bi2)
{
    __shared__ float s_bias1[128], s_bias2[128];
    __shared__ unsigned char s_vf[128];

    const int t    = threadIdx.x;
    const int lane = t & 31;
    const int w    = t >> 5;
    const int row0 = blockIdx.x * 128;
    const int b    = row0 / NC;
    const uint32_t sbase = smem_u32(sdyn);

    {
        const float4* ws = (const float4*)g_wT;
        float4* wd = (float4*)(sdyn + W_OFF);
        #pragma unroll
        for (int i = 0; i < 34; i++) wd[t + i * 256] = ws[t + i * 256];
    }
    {
        const float4* xg = (const float4*)(x + (size_t)row0 * 128);
        #pragma unroll
        for (int i = 0; i < 16; i++) {
            int fidx = t + i * 256;
            float4 v = xg[fidx];
            int row = fidx >> 5;
            int k   = (fidx & 31) * 4;
            uint32_t hA = pack_bf2(v.x, v.y);
            uint32_t hB = pack_bf2(v.z, v.w);
            uint32_t lA = pack_bf2(v.x - bfhi(v.x), v.y - bfhi(v.y));
            uint32_t lB = pack_bf2(v.z - bfhi(v.z), v.w - bfhi(v.w));
            size_t off = ((size_t)row * WST + k) * 2;
            *(u64*)(sdyn + AHI_OFF + off) = ((u64)hB << 32) | hA;
            *(u64*)(sdyn + ALO_OFF + off) = ((u64)lB << 32) | lA;
        }
    }
    if (t < 128) {
        s_bias1[t] = bi1[t];
        s_bias2[t] = bi2[t];
        const int lenb = g_len[b];
        const int rem = row0 + t - b * NC;
        const int i  = rem / 1600;
        const int j  = (rem / 40) % 40;
        const int kk = rem % 40;
        s_vf[t] = (i < j) && (j < kk) && (kk < lenb);
    }
    __syncthreads();

    const int m0 = w * 16;
    const int c2 = (lane & 3) * 2;
    const uint32_t aHi = sbase + AHI_OFF + (((m0 + (lane & 15)) * WST + (lane >> 4) * 8) << 1);
    const uint32_t aLo = aHi + (ALO_OFF - AHI_OFF);
    // paired-B x4 address: lanes 0-15 -> n rows [nt*8, +8), lanes 16-31 -> [nt*8+8, +8)
    const uint32_t bPr = sbase + W_OFF +
        (((((lane & 7) + ((lane >> 4) << 3)) * WST) + ((lane >> 3) & 1) * 8) << 1);

    float acc[16][4];
    #pragma unroll
    for (int nt = 0; nt < 16; nt++)
        acc[nt][0] = acc[nt][1] = acc[nt][2] = acc[nt][3] = 0.f;

    #pragma unroll
    for (int ks = 0; ks < 8; ks++) {
        uint32_t ahi[4], alo[4];
        ldsm_x4(aHi + ks * 32, ahi);
        ldsm_x4(aLo + ks * 32, alo);
        #pragma unroll
        for (int nt = 0; nt < 16; nt += 2) {
            uint32_t bh[4], bl[4];
            ldsm_x4(bPr + 0 * WIMG + nt * (8 * WST * 2) + ks * 32, bh);
            ldsm_x4(bPr + 1 * WIMG + nt * (8 * WST * 2) + ks * 32, bl);
            mma16816(acc[nt], ahi, bh);     mma16816(acc[nt + 1], ahi, bh + 2);
            mma16816(acc[nt], ahi, bl);     mma16816(acc[nt + 1], ahi, bl + 2);
            mma16816(acc[nt], alo, bh);     mma16816(acc[nt + 1], alo, bh + 2);
        }
    }
    __syncthreads();

    uint32_t a2h[8][4], a2l[8][4];
    #pragma unroll
    for (int ks = 0; ks < 8; ks++) {
        #pragma unroll
        for (int h = 0; h < 2; h++) {
            const int nt = 2 * ks + h;
            const float b0 = s_bias1[nt * 8 + c2];
            const float b1 = s_bias1[nt * 8 + c2 + 1];
            float f0 = fmaxf(acc[nt][0] + b0, 0.f);
            float f1 = fmaxf(acc[nt][1] + b1, 0.f);
            float f2 = fmaxf(acc[nt][2] + b0, 0.f);
            float f3 = fmaxf(acc[nt][3] + b1, 0.f);
            a2h[ks][0 + 2 * h] = pack_bf2(f0, f1);
            a2h[ks][1 + 2 * h] = pack_bf2(f2, f3);
            a2l[ks][0 + 2 * h] = pack_bf2(f0 - bfhi(f0), f1 - bfhi(f1));
            a2l[ks][1 + 2 * h] = pack_bf2(f2 - bfhi(f2), f3 - bfhi(f3));
        }
    }

    #pragma unroll
    for (int nt = 0; nt < 16; nt++)
        acc[nt][0] = acc[nt][1] = acc[nt][2] = acc[nt][3] = 0.f;
    #pragma unroll
    for (int ks = 0; ks < 8; ks++) {
        #pragma unroll
        for (int nt = 0; nt < 16; nt += 2) {
            uint32_t bh[4], bl[4];
            ldsm_x4(bPr + 2 * WIMG + nt * (8 * WST * 2) + ks * 32, bh);
            ldsm_x4(bPr + 3 * WIMG + nt * (8 * WST * 2) + ks * 32, bl);
            mma16816(acc[nt], a2h[ks], bh); mma16816(acc[nt + 1], a2h[ks], bh + 2);
            mma16816(acc[nt], a2h[ks], bl); mma16816(acc[nt + 1], a2h[ks], bl + 2);
            mma16816(acc[nt], a2l[ks], bh); mma16816(acc[nt + 1], a2l[ks], bh + 2);
        }
    }

    float* sxf = (float*)sdyn;
    const int g = lane >> 2;
    #pragma unroll
    for (int nt = 0; nt < 16; nt++) {
        const int nc = nt * 8 + c2;
        const float b0 = s_bias2[nc], b1 = s_bias2[nc + 1];
        *(float2*)(&sxf[(m0 + g) * SXF_STRIDE + nc])     = make_float2(acc[nt][0] + b0, acc[nt][1] + b1);
        *(float2*)(&sxf[(m0 + g + 8) * SXF_STRIDE + nc]) = make_float2(acc[nt][2] + b0, acc[nt][3] + b1);
    }
    __syncthreads();

    {
        float4* xo = (float4*)(g_xembed + (size_t)row0 * 128);
        #pragma unroll
        for (int i = 0; i < 16; i++) {
            int idx = t + i * 256;
            int row = idx >> 5;
            int c4  = (idx & 31) * 4;
            const float* p = &sxf[row * SXF_STRIDE + c4];
            xo[idx] = make_float4(p[0], p[1], p[2], p[3]);
        }
    }
    if (t < 128) {
        float s = 0.f;
        for (int r = 0; r < 128; r++)
            if (s_vf[r]) s += __expf(sxf[r * SXF_STRIDE + t]);
        if (s != 0.f) atomicAdd(&g_sumexp[b * 128 + t], s);
    }
}

// ---------------------------------------------------------------------------
// Kernel 2 (HMMA): out = relu([a*relu(xf@We), xf]@Wo1+bo1)@Wo2+bo2
// XF images persist at smem[0..69632); Wo1 half-buffers live above them so
// xf A-fragments are re-loaded via ldmatrix (cuts register pressure);
// 4 interleaved accumulators break the HMMA dependency chain.
// ---------------------------------------------------------------------------
#define XFHI 0
#define XFLO 34816
#define AXHI 69632
#define AXLO 104448
#define WEHI 139264
#define WELO 174080
#define WO1HI 69632
#define WO1LO 137216     // 69632 + 128*264*2

__global__ __launch_bounds__(256, 1) void k_out_hmma(
    const float* __restrict__ bo1,
    const float* __restrict__ Wo2, const float* __restrict__ bo2,
    float* __restrict__ out)
{
    __shared__ float s_bo1[256], s_wo2[256], s_inv[128];
    __shared__ unsigned char s_vf[128];

    const int t    = threadIdx.x;
    const int lane = t & 31;
    const int w    = t >> 5;
    const int row0 = blockIdx.x * 128;
    const int b    = row0 / NC;
    const uint32_t sbase = smem_u32(sdyn);

    if (t < 128) {
        s_inv[t] = 1.0f / g_sumexp[b * 128 + t];
        const int lenb = g_len[b];
        const int rem = row0 + t - b * NC;
        const int i  = rem / 1600;
        const int j  = (rem / 40) % 40;
        const int kk = rem % 40;
        s_vf[t] = (i < j) && (j < kk) && (kk < lenb);
    }
    s_bo1[t] = bo1[t];
    s_wo2[t] = Wo2[t];
    const int bany = __syncthreads_or((t < 128) ? (int)s_vf[t] : 0);

    // xf tile -> bf16 hi/lo images
    {
        const float4* xg = (const float4*)(g_xembed + (size_t)row0 * 128);
        #pragma unroll
        for (int i = 0; i < 16; i++) {
            int fidx = t + i * 256;
            float4 v = xg[fidx];
            int row = fidx >> 5;
            int k   = (fidx & 31) * 4;
            uint32_t hA = pack_bf2(v.x, v.y);
            uint32_t hB = pack_bf2(v.z, v.w);
            uint32_t lA = pack_bf2(v.x - bfhi(v.x), v.y - bfhi(v.y));
            uint32_t lB = pack_bf2(v.z - bfhi(v.z), v.w - bfhi(v.w));
            size_t off = ((size_t)row * WST + k) * 2;
            *(u64*)(sdyn + XFHI + off) = ((u64)hB << 32) | hA;
            *(u64*)(sdyn + XFLO + off) = ((u64)lB << 32) | lA;
        }
    }
    if (bany) {
        const float4* ws = (const float4*)g_weT;
        float4* wd = (float4*)(sdyn + WEHI);
        #pragma unroll
        for (int i = 0; i < 17; i++) wd[t + i * 256] = ws[t + i * 256];
    }
    __syncthreads();

    const int m0 = w * 16;
    const int c2 = (lane & 3) * 2;
    const int g  = lane >> 2;
    const uint32_t aAddr = sbase + (((m0 + (lane & 15)) * WST + (lane >> 4) * 8) << 1);
    const uint32_t bPr136 = sbase +
        (((((lane & 7) + ((lane >> 4) << 3)) * WST) + ((lane >> 3) & 1) * 8) << 1);

    const int vlane = s_vf[m0 + (lane & 15)];
    const int warp_any = __any_sync(0xffffffffu, vlane);

    // ---- stage A: axi = a .* relu(xf @ We), 4 interleaved accumulators ----
    uint32_t axh[8][4], axl[8][4];
    if (warp_any) {
        const int r0 = m0 + g, r1 = m0 + g + 8;
        const bool v0 = s_vf[r0], v1 = s_vf[r1];
        #pragma unroll
        for (int ntg = 0; ntg < 16; ntg += 4) {
            float acc[4][4];
            #pragma unroll
            for (int q = 0; q < 4; q++)
                acc[q][0] = acc[q][1] = acc[q][2] = acc[q][3] = 0.f;
            #pragma unroll
            for (int ks = 0; ks < 8; ks++) {
                uint32_t ah[4], al[4];
                ldsm_x4(aAddr + XFHI + ks * 32, ah);
                ldsm_x4(aAddr + XFLO + ks * 32, al);
                uint32_t bhA[4], bhB[4], blA[4], blB[4];
                ldsm_x4(bPr136 + WEHI + (ntg + 0) * (8 * WST * 2) + ks * 32, bhA);
                ldsm_x4(bPr136 + WEHI + (ntg + 2) * (8 * WST * 2) + ks * 32, bhB);
                ldsm_x4(bPr136 + WELO + (ntg + 0) * (8 * WST * 2) + ks * 32, blA);
                ldsm_x4(bPr136 + WELO + (ntg + 2) * (8 * WST * 2) + ks * 32, blB);
                mma16816(acc[0], ah, bhA);     mma16816(acc[1], ah, bhA + 2);
                mma16816(acc[2], ah, bhB);     mma16816(acc[3], ah, bhB + 2);
                mma16816(acc[0], ah, blA);     mma16816(acc[1], ah, blA + 2);
                mma16816(acc[2], ah, blB);     mma16816(acc[3], ah, blB + 2);
                mma16816(acc[0], al, bhA);     mma16816(acc[1], al, bhA + 2);
                mma16816(acc[2], al, bhB);     mma16816(acc[3], al, bhB + 2);
            }
            #pragma unroll
            for (int q = 0; q < 4; q++) {
                const int c = (ntg + q) * 8 + c2;
                const float i0 = s_inv[c], i1 = s_inv[c + 1];
                float v00 = 0.f, v01 = 0.f, v10 = 0.f, v11 = 0.f;
                if (v0) {
                    __nv_bfloat162 h = *(__nv_bfloat162*)(sdyn + XFHI + ((r0 * WST + c) << 1));
                    __nv_bfloat162 l = *(__nv_bfloat162*)(sdyn + XFLO + ((r0 * WST + c) << 1));
                    float x0 = __bfloat162float(h.x) + __bfloat162float(l.x);
                    float x1 = __bfloat162float(h.y) + __bfloat162float(l.y);
                    v00 = __expf(x0) * i0 * fmaxf(acc[q][0], 0.f);
                    v01 = __expf(x1) * i1 * fmaxf(acc[q][1], 0.f);
                }
                if (v1) {
                    __nv_bfloat162 h = *(__nv_bfloat162*)(sdyn + XFHI + ((r1 * WST + c) << 1));
                    __nv_bfloat162 l = *(__nv_bfloat162*)(sdyn + XFLO + ((r1 * WST + c) << 1));
                    float x0 = __bfloat162float(h.x) + __bfloat162float(l.x);
                    float x1 = __bfloat162float(h.y) + __bfloat162float(l.y);
                    v10 = __expf(x0) * i0 * fmaxf(acc[q][2], 0.f);
                    v11 = __expf(x1) * i1 * fmaxf(acc[q][3], 0.f);
                }
                *(uint32_t*)(sdyn + AXHI + ((r0 * WST + c) << 1)) = pack_bf2(v00, v01);
                *(uint32_t*)(sdyn + AXLO + ((r0 * WST + c) << 1)) = pack_bf2(v00 - bfhi(v00), v01 - bfhi(v01));
                *(uint32_t*)(sdyn + AXHI + ((r1 * WST + c) << 1)) = pack_bf2(v10, v11);
                *(uint32_t*)(sdyn + AXLO + ((r1 * WST + c) << 1)) = pack_bf2(v10 - bfhi(v10), v11 - bfhi(v11));
            }
        }
        __syncwarp();
        #pragma unroll
        for (int ks = 0; ks < 8; ks++) {
            ldsm_x4(aAddr + AXHI + ks * 32, axh[ks]);
            ldsm_x4(aAddr + AXLO + ks * 32, axl[ks]);
        }
    }

    // ---- stage B: two 128-col halves of Wo1; xf frags reloaded from smem ----
    float rsum0 = 0.f, rsum1 = 0.f;
    const uint32_t bPr264 = sbase +
        (((((lane & 7) + ((lane >> 4) << 3)) * 264) + ((lane >> 3) & 1) * 8) << 1);

    #pragma unroll
    for (int half = 0; half < 2; half++) {
        __syncthreads();   // prior reads of [WO1HI..] region complete
        #pragma unroll
        for (int img = 0; img < 2; img++) {
            const uint4* src = (const uint4*)(g_wo1T[img] + (half * 128) * 256);
            const uint32_t dst0 = (img ? WO1LO : WO1HI);
            #pragma unroll
            for (int i = 0; i < 16; i++) {
                int e = t + i * 256;
                int r = e >> 5;
                int kq = (e & 31) * 8;
                *(uint4*)(sdyn + dst0 + ((r * 264 + kq) << 1)) = src[e];
            }
        }
        __syncthreads();

        #pragma unroll
        for (int ntg = 0; ntg < 16; ntg += 4) {
            float acc[4][4];
            #pragma unroll
            for (int q = 0; q < 4; q++)
                acc[q][0] = acc[q][1] = acc[q][2] = acc[q][3] = 0.f;
            #pragma unroll
            for (int ks = 0; ks < 8; ks++) {
                uint32_t ah[4], al[4];
                ldsm_x4(aAddr + XFHI + ks * 32, ah);
                ldsm_x4(aAddr + XFLO + ks * 32, al);
                // xf part: Wo1 rows k = 128 + ks*16
                {
                    uint32_t bhA[4], bhB[4], blA[4], blB[4];
                    const uint32_t ko = (128 + ks * 16) * 2;
                    ldsm_x4(bPr264 + WO1HI + (ntg + 0) * (8 * 264 * 2) + ko, bhA);
                    ldsm_x4(bPr264 + WO1HI + (ntg + 2) * (8 * 264 * 2) + ko, bhB);
                    ldsm_x4(bPr264 + WO1LO + (ntg + 0) * (8 * 264 * 2) + ko, blA);
                    ldsm_x4(bPr264 + WO1LO + (ntg + 2) * (8 * 264 * 2) + ko, blB);
                    mma16816(acc[0], ah, bhA);  mma16816(acc[1], ah, bhA + 2);
                    mma16816(acc[2], ah, bhB);  mma16816(acc[3], ah, bhB + 2);
                    mma16816(acc[0], ah, blA);  mma16816(acc[1], ah, blA + 2);
                    mma16816(acc[2], ah, blB);  mma16816(acc[3], ah, blB + 2);
                    mma16816(acc[0], al, bhA);  mma16816(acc[1], al, bhA + 2);
                    mma16816(acc[2], al, bhB);  mma16816(acc[3], al, bhB + 2);
                }
                // a*x_inner part: Wo1 rows k = ks*16 (warp-uniform skip)
                if (warp_any) {
                    uint32_t bhA[4], bhB[4], blA[4], blB[4];
                    const uint32_t ko = (ks * 16) * 2;
                    ldsm_x4(bPr264 + WO1HI + (ntg + 0) * (8 * 264 * 2) + ko, bhA);
                    ldsm_x4(bPr264 + WO1HI + (ntg + 2) * (8 * 264 * 2) + ko, bhB);
                    ldsm_x4(bPr264 + WO1LO + (ntg + 0) * (8 * 264 * 2) + ko, blA);
                    ldsm_x4(bPr264 + WO1LO + (ntg + 2) * (8 * 264 * 2) + ko, blB);
                    mma16816(acc[0], axh[ks], bhA);  mma16816(acc[1], axh[ks], bhA + 2);
                    mma16816(acc[2], axh[ks], bhB);  mma16816(acc[3], axh[ks], bhB + 2);
                    mma16816(acc[0], axh[ks], blA);  mma16816(acc[1], axh[ks], blA + 2);
                    mma16816(acc[2], axh[ks], blB);  mma16816(acc[3], axh[ks], blB + 2);
                    mma16816(acc[0], axl[ks], bhA);  mma16816(acc[1], axl[ks], bhA + 2);
                    mma16816(acc[2], axl[ks], bhB);  mma16816(acc[3], axl[ks], bhB + 2);
                }
            }
            #pragma unroll
            for (int q = 0; q < 4; q++) {
                const int col = half * 128 + (ntg + q) * 8 + c2;
                const float g0 = fmaxf(acc[q][0] + s_bo1[col],     0.f);
                const float g1 = fmaxf(acc[q][1] + s_bo1[col + 1], 0.f);
                const float g2 = fmaxf(acc[q][2] + s_bo1[col],     0.f);
                const float g3 = fmaxf(acc[q][3] + s_bo1[col + 1], 0.f);
                rsum0 += g0 * s_wo2[col] + g1 * s_wo2[col + 1];
                rsum1 += g2 * s_wo2[col] + g3 * s_wo2[col + 1];
            }
        }
    }

    rsum0 += __shfl_xor_sync(0xffffffffu, rsum0, 1);
    rsum0 += __shfl_xor_sync(0xffffffffu, rsum0, 2);
    rsum1 += __shfl_xor_sync(0xffffffffu, rsum1, 1);
    rsum1 += __shfl_xor_sync(0xffffffffu, rsum1, 2);
    if ((lane & 3) == 0) {
        const float b2 = bo2[0];
        out[row0 + m0 + g]     = rsum0 + b2;
        out[row0 + m0 + g + 8] = rsum1 + b2;
    }
}

// ---------------------------------------------------------------------------
extern "C" void kernel_launch(void* const* d_in, const int* in_sizes, int n_in,
                              void* d_out, int out_size) {
    const float* x          = (const float*)d_in[0];
    const unsigned char* mk = (const unsigned char*)d_in[1];
    const float* Wi1        = (const float*)d_in[2];
    const float* bi1        = (const float*)d_in[3];
    const float* Wi2        = (const float*)d_in[4];
    const float* bi2        = (const float*)d_in[5];
    const float* We         = (const float*)d_in[6];
    const float* Wo1        = (const float*)d_in[7];
    const float* bo1        = (const float*)d_in[8];
    const float* Wo2        = (const float*)d_in[9];
    const float* bo2        = (const float*)d_in[10];
    float* out              = (float*)d_out;

    cudaFuncSetAttribute(k_embed_hmma, cudaFuncAttributeMaxDynamicSharedMemorySize, DSMEM);
    cudaFuncSetAttribute(k_out_hmma, cudaFuncAttributeMaxDynamicSharedMemorySize, DSMEM);

    const int prep_elems = 6 * 128 * WST + 2 * 65536;
    k_setup<<<1, 512>>>(mk);
    k_prep<<<(prep_elems + 255) / 256, 256>>>(Wi1, Wi2, We, Wo1);
    k_embed_hmma<<<RT / 128, 256, DSMEM>>>(x, bi1, bi2);
    k_out_hmma<<<RT / 128, 256, DSMEM>>>(bo1, Wo2, bo2, out);
}